// round 1
// baseline (speedup 1.0000x reference)
#include <cuda_runtime.h>
#include <cuda_bf16.h>
#include <math.h>

// Problem constants
#define BATCH 2
#define SEQ   2048
#define DIM   1024
#define HEADS 16
#define HDIM  64
#define BH    (BATCH*HEADS)          // 32
#define MROWS (BATCH*SEQ)            // 4096
#define QKVN  (3*DIM)                // 3072

// ---------------- scratch (device globals; no allocation allowed) -------------
__device__ float g_qkv[MROWS * QKVN];          // 48 MB  [4096][3072]
__device__ float g_q[BH * SEQ * HDIM];         // [bh][n][d]
__device__ float g_k[BH * SEQ * HDIM];
__device__ float g_v[BH * SEQ * HDIM];
__device__ float g_o[BH * SEQ * HDIM];
__device__ float g_ln[MROWS * DIM];            // LN output [4096][1024]
__device__ float g_bias3[QKVN];

// ---------------- merged qkv bias ---------------------------------------------
__global__ void make_bias3_kernel(const float* __restrict__ qb,
                                  const float* __restrict__ vb) {
    int i = blockIdx.x * 256 + threadIdx.x;
    if (i >= QKVN) return;
    float v = 0.0f;
    if (i < DIM) v = qb[i];
    else if (i >= 2*DIM) v = vb[i - 2*DIM];
    g_bias3[i] = v;
}

// ---------------- SGEMM  C[M][N] = A[M][K] * B[N][K]^T + bias[n] ---------------
// 128x128x16 tile, 256 threads, 8x8 microtile, k-major smem, float4 fragments.
#define GBM 128
#define GBN 128
#define GBK 16

__global__ __launch_bounds__(256)
void sgemm_nt_kernel(const float* __restrict__ A, const float* __restrict__ B,
                     const float* __restrict__ bias, float* __restrict__ C,
                     int M, int N, int K) {
    __shared__ float As[GBK][GBM + 4];
    __shared__ float Bs[GBK][GBN + 4];

    const int tid = threadIdx.x;
    const int tx = tid & 15;       // n group
    const int ty = tid >> 4;       // m group
    const int m0 = blockIdx.y * GBM;
    const int n0 = blockIdx.x * GBN;
    const int mi0 = ty * 4;
    const int ni0 = tx * 4;

    float acc[8][8];
#pragma unroll
    for (int i = 0; i < 8; i++)
#pragma unroll
        for (int j = 0; j < 8; j++) acc[i][j] = 0.0f;

    for (int kb = 0; kb < K; kb += GBK) {
        // load A tile (128 rows x 16 cols) as 512 float4, transpose to k-major
#pragma unroll
        for (int t = 0; t < 2; t++) {
            int idx = tid + t * 256;            // 0..511
            int row = idx >> 2;
            int c4  = idx & 3;
            float4 v = *(const float4*)&A[(size_t)(m0 + row) * K + kb + c4 * 4];
            As[c4*4+0][row] = v.x; As[c4*4+1][row] = v.y;
            As[c4*4+2][row] = v.z; As[c4*4+3][row] = v.w;
        }
#pragma unroll
        for (int t = 0; t < 2; t++) {
            int idx = tid + t * 256;
            int row = idx >> 2;
            int c4  = idx & 3;
            float4 v = *(const float4*)&B[(size_t)(n0 + row) * K + kb + c4 * 4];
            Bs[c4*4+0][row] = v.x; Bs[c4*4+1][row] = v.y;
            Bs[c4*4+2][row] = v.z; Bs[c4*4+3][row] = v.w;
        }
        __syncthreads();

#pragma unroll
        for (int k = 0; k < GBK; k++) {
            float a[8], b[8];
            *(float4*)&a[0] = *(const float4*)&As[k][mi0];
            *(float4*)&a[4] = *(const float4*)&As[k][64 + mi0];
            *(float4*)&b[0] = *(const float4*)&Bs[k][ni0];
            *(float4*)&b[4] = *(const float4*)&Bs[k][64 + ni0];
#pragma unroll
            for (int i = 0; i < 8; i++)
#pragma unroll
                for (int j = 0; j < 8; j++)
                    acc[i][j] = fmaf(a[i], b[j], acc[i][j]);
        }
        __syncthreads();
    }

    // epilogue: add bias, store
#pragma unroll
    for (int i = 0; i < 8; i++) {
        int m = m0 + ((i < 4) ? (mi0 + i) : (64 + mi0 + i - 4));
#pragma unroll
        for (int jj = 0; jj < 2; jj++) {
            int n = n0 + ((jj == 0) ? ni0 : (64 + ni0));
            float4 v;
            v.x = acc[i][jj*4+0] + bias[n+0];
            v.y = acc[i][jj*4+1] + bias[n+1];
            v.z = acc[i][jj*4+2] + bias[n+2];
            v.w = acc[i][jj*4+3] + bias[n+3];
            *(float4*)&C[(size_t)m * N + n] = v;
        }
    }
}

// ---------------- QKV split + RoPE scatter -------------------------------------
// one thread per (bh, n, d2): 32*2048*32 = 2^21 threads
__global__ void qkv_rope_kernel(const float* __restrict__ pe) {
    int idx = blockIdx.x * 256 + threadIdx.x;
    int d2 = idx & 31;
    int n  = (idx >> 5) & 2047;
    int bh = idx >> 16;                 // 0..31
    int b = bh >> 4;
    int h = bh & 15;

    size_t src = ((size_t)(b * SEQ + n)) * QKVN + h * HDIM + d2 * 2;
    float q0 = g_qkv[src],        q1 = g_qkv[src + 1];
    float k0 = g_qkv[src + DIM],  k1 = g_qkv[src + DIM + 1];
    float v0 = g_qkv[src + 2*DIM], v1 = g_qkv[src + 2*DIM + 1];

    const float* p = &pe[((size_t)n * 32 + d2) * 4];  // [n][d2][2][2]
    float p00 = p[0], p01 = p[1], p10 = p[2], p11 = p[3];

    size_t dst = ((size_t)bh * SEQ + n) * HDIM + d2 * 2;
    g_q[dst]     = p00 * q0 + p01 * q1;
    g_q[dst + 1] = p10 * q0 + p11 * q1;
    g_k[dst]     = p00 * k0 + p01 * k1;
    g_k[dst + 1] = p10 * k0 + p11 * k1;
    g_v[dst]     = v0;
    g_v[dst + 1] = v1;
}

// ---------------- k_mean over heads --------------------------------------------
// one thread per (b, n, d): 2*2048*64 = 262144
__global__ void kmean_kernel(float* __restrict__ out) {
    int idx = blockIdx.x * 256 + threadIdx.x;
    int d = idx & 63;
    int n = (idx >> 6) & 2047;
    int b = idx >> 17;
    float s = 0.0f;
#pragma unroll
    for (int h = 0; h < HEADS; h++)
        s += g_k[(((size_t)(b * HEADS + h)) * SEQ + n) * HDIM + d];
    out[idx] = s * (1.0f / 16.0f);
}

// ---------------- flash attention (fp32, 64x64 tiles, online softmax) ----------
// grid: (32 q-tiles, 32 bh), 256 threads, 4x4 microtile
#define FPAD 68
__global__ __launch_bounds__(256)
void flash_attn_kernel() {
    extern __shared__ float smem[];
    float (*Qs)[FPAD] = (float(*)[FPAD])(smem);                 // [d][m]
    float (*Ks)[FPAD] = (float(*)[FPAD])(smem + 64 * FPAD);     // [d][n]
    float (*Vs)[FPAD] = (float(*)[FPAD])(smem + 2 * 64 * FPAD); // [n][d]
    float (*Ps)[FPAD] = (float(*)[FPAD])(smem + 3 * 64 * FPAD); // [n][m]

    const int tid = threadIdx.x;
    const int tx = tid & 15;
    const int ty = tid >> 4;
    const int bh = blockIdx.y;
    const int m0 = blockIdx.x * 64;

    const float* Qb = g_q + (size_t)bh * SEQ * HDIM;
    const float* Kb = g_k + (size_t)bh * SEQ * HDIM;
    const float* Vb = g_v + (size_t)bh * SEQ * HDIM;

    // load Q tile transposed: Qs[d][m]
#pragma unroll
    for (int t = 0; t < 4; t++) {
        int idx = tid + t * 256;          // 0..1023 float4 slots
        int row = idx >> 4;
        int c4  = idx & 15;
        float4 v = *(const float4*)&Qb[(size_t)(m0 + row) * HDIM + c4 * 4];
        Qs[c4*4+0][row] = v.x; Qs[c4*4+1][row] = v.y;
        Qs[c4*4+2][row] = v.z; Qs[c4*4+3][row] = v.w;
    }

    float mi[4], li[4], o[4][4];
#pragma unroll
    for (int i = 0; i < 4; i++) {
        mi[i] = -1e30f; li[i] = 0.0f;
#pragma unroll
        for (int j = 0; j < 4; j++) o[i][j] = 0.0f;
    }
    const float scale = 0.125f;   // 1/sqrt(64)

    for (int n0 = 0; n0 < SEQ; n0 += 64) {
        __syncthreads();   // previous PV done (Vs/Ps reusable); also guards Qs on iter 0
        // load K tile transposed, V tile natural
#pragma unroll
        for (int t = 0; t < 4; t++) {
            int idx = tid + t * 256;
            int row = idx >> 4;
            int c4  = idx & 15;
            float4 v = *(const float4*)&Kb[(size_t)(n0 + row) * HDIM + c4 * 4];
            Ks[c4*4+0][row] = v.x; Ks[c4*4+1][row] = v.y;
            Ks[c4*4+2][row] = v.z; Ks[c4*4+3][row] = v.w;
            float4 w = *(const float4*)&Vb[(size_t)(n0 + row) * HDIM + c4 * 4];
            *(float4*)&Vs[row][c4*4] = w;
        }
        __syncthreads();

        // S = Q K^T  (4x4 per thread)
        float s[4][4];
#pragma unroll
        for (int i = 0; i < 4; i++)
#pragma unroll
            for (int j = 0; j < 4; j++) s[i][j] = 0.0f;

#pragma unroll 16
        for (int d = 0; d < HDIM; d++) {
            float a[4], b[4];
            *(float4*)a = *(const float4*)&Qs[d][ty*4];
            *(float4*)b = *(const float4*)&Ks[d][tx*4];
#pragma unroll
            for (int i = 0; i < 4; i++)
#pragma unroll
                for (int j = 0; j < 4; j++)
                    s[i][j] = fmaf(a[i], b[j], s[i][j]);
        }

        // online softmax update per row
#pragma unroll
        for (int i = 0; i < 4; i++) {
#pragma unroll
            for (int j = 0; j < 4; j++) s[i][j] *= scale;
            float rm = fmaxf(fmaxf(s[i][0], s[i][1]), fmaxf(s[i][2], s[i][3]));
#pragma unroll
            for (int msk = 1; msk < 16; msk <<= 1)
                rm = fmaxf(rm, __shfl_xor_sync(0xffffffffu, rm, msk));
            float mn = fmaxf(mi[i], rm);
            float alpha = __expf(mi[i] - mn);
            float rs = 0.0f;
#pragma unroll
            for (int j = 0; j < 4; j++) {
                s[i][j] = __expf(s[i][j] - mn);
                rs += s[i][j];
            }
#pragma unroll
            for (int msk = 1; msk < 16; msk <<= 1)
                rs += __shfl_xor_sync(0xffffffffu, rs, msk);
            li[i] = li[i] * alpha + rs;
            mi[i] = mn;
#pragma unroll
            for (int j = 0; j < 4; j++) o[i][j] *= alpha;
        }

        // write P transposed: Ps[n][m]
#pragma unroll
        for (int j = 0; j < 4; j++) {
            float4 v = make_float4(s[0][j], s[1][j], s[2][j], s[3][j]);
            *(float4*)&Ps[tx*4 + j][ty*4] = v;
        }
        __syncthreads();

        // O += P V
#pragma unroll 8
        for (int n = 0; n < 64; n++) {
            float p[4], vv[4];
            *(float4*)p  = *(const float4*)&Ps[n][ty*4];
            *(float4*)vv = *(const float4*)&Vs[n][tx*4];
#pragma unroll
            for (int i = 0; i < 4; i++)
#pragma unroll
                for (int j = 0; j < 4; j++)
                    o[i][j] = fmaf(p[i], vv[j], o[i][j]);
        }
    }

    // normalize + store
    float* Ob = g_o + (size_t)bh * SEQ * HDIM;
#pragma unroll
    for (int i = 0; i < 4; i++) {
        float inv = 1.0f / li[i];
        float4 v = make_float4(o[i][0]*inv, o[i][1]*inv, o[i][2]*inv, o[i][3]*inv);
        *(float4*)&Ob[(size_t)(m0 + ty*4 + i) * HDIM + tx*4] = v;
    }
}

// ---------------- LayerNorm (gather heads -> [b][n][1024] row) -----------------
__global__ __launch_bounds__(256)
void ln_kernel(const float* __restrict__ gamma, const float* __restrict__ beta) {
    int bn = blockIdx.x;                 // 0..4095
    int b = bn >> 11;
    int n = bn & 2047;

    float vals[4];
    float s = 0.0f, ss = 0.0f;
#pragma unroll
    for (int t = 0; t < 4; t++) {
        int c = threadIdx.x + t * 256;
        int h = c >> 6, d = c & 63;
        float v = g_o[(((size_t)(b * HEADS + h)) * SEQ + n) * HDIM + d];
        vals[t] = v; s += v; ss += v * v;
    }
    // block reduce
#pragma unroll
    for (int m = 16; m; m >>= 1) {
        s  += __shfl_xor_sync(0xffffffffu, s, m);
        ss += __shfl_xor_sync(0xffffffffu, ss, m);
    }
    __shared__ float rs[8], rss[8];
    int w = threadIdx.x >> 5, lane = threadIdx.x & 31;
    if (lane == 0) { rs[w] = s; rss[w] = ss; }
    __syncthreads();
    float st = 0.0f, sst = 0.0f;
#pragma unroll
    for (int i = 0; i < 8; i++) { st += rs[i]; sst += rss[i]; }

    float mean = st * (1.0f / 1024.0f);
    float var  = sst * (1.0f / 1024.0f) - mean * mean;
    float r = rsqrtf(var + 1e-5f);
#pragma unroll
    for (int t = 0; t < 4; t++) {
        int c = threadIdx.x + t * 256;
        g_ln[(size_t)bn * DIM + c] = (vals[t] - mean) * r * gamma[c] + beta[c];
    }
}

// ---------------- launch --------------------------------------------------------
extern "C" void kernel_launch(void* const* d_in, const int* in_sizes, int n_in,
                              void* d_out, int out_size) {
    const float* x      = (const float*)d_in[0];
    const float* pe     = (const float*)d_in[1];
    const float* qkv_w  = (const float*)d_in[2];
    const float* q_bias = (const float*)d_in[3];
    const float* v_bias = (const float*)d_in[4];
    const float* gamma  = (const float*)d_in[5];
    const float* beta   = (const float*)d_in[6];
    const float* proj_w = (const float*)d_in[7];
    const float* proj_b = (const float*)d_in[8];
    float* out = (float*)d_out;

    void *p_qkv, *p_ln, *p_bias3;
    cudaGetSymbolAddress(&p_qkv, g_qkv);
    cudaGetSymbolAddress(&p_ln, g_ln);
    cudaGetSymbolAddress(&p_bias3, g_bias3);

    // raise dynamic smem limit for flash attention (69.6 KB)
    static const size_t FLASH_SMEM = 4 * 64 * FPAD * sizeof(float);
    cudaFuncSetAttribute(flash_attn_kernel,
                         cudaFuncAttributeMaxDynamicSharedMemorySize,
                         (int)FLASH_SMEM);

    // 1) merged qkv bias
    make_bias3_kernel<<<(QKVN + 255) / 256, 256>>>(q_bias, v_bias);

    // 2) QKV GEMM: [4096,1024] x [3072,1024]^T
    sgemm_nt_kernel<<<dim3(QKVN / GBN, MROWS / GBM), 256>>>(
        x, qkv_w, (const float*)p_bias3, (float*)p_qkv, MROWS, QKVN, DIM);

    // 3) split + RoPE
    qkv_rope_kernel<<<(BH * SEQ * 32) / 256, 256>>>(pe);

    // 4) k_mean side output
    kmean_kernel<<<(BATCH * SEQ * HDIM) / 256, 256>>>(out + (size_t)MROWS * DIM);

    // 5) attention
    flash_attn_kernel<<<dim3(SEQ / 64, BH), 256, FLASH_SMEM>>>();

    // 6) layernorm (also gathers heads back to [b][n][c])
    ln_kernel<<<MROWS, 256>>>(gamma, beta);

    // 7) projection GEMM -> d_out
    sgemm_nt_kernel<<<dim3(DIM / GBN, MROWS / GBM), 256>>>(
        (const float*)p_ln, proj_w, proj_b, out, MROWS, DIM, DIM);
}

// round 3
// speedup vs baseline: 1.8576x; 1.8576x over previous
#include <cuda_runtime.h>
#include <cuda_bf16.h>
#include <math.h>

#define BATCH 2
#define SEQ   2048
#define DIM   1024
#define HEADS 16
#define HDIM  64
#define BH    (BATCH*HEADS)          // 32
#define MROWS (BATCH*SEQ)            // 4096
#define QKVN  (3*DIM)                // 3072

typedef unsigned short ushortT;
typedef unsigned int   u32;

// ---------------- scratch (device globals) -------------------------------------
__device__ float   g_qkv[MROWS * QKVN];            // fp32 qkv output
__device__ float   g_o[BH * SEQ * HDIM];           // attention out [bh][n][d]
__device__ float   g_bias3[QKVN];
__device__ ushortT g_xh[MROWS * DIM],  g_xl[MROWS * DIM];
__device__ ushortT g_wh[QKVN * DIM],   g_wl[QKVN * DIM];
__device__ ushortT g_pwh[DIM * DIM],   g_pwl[DIM * DIM];
__device__ ushortT g_qh[BH*SEQ*HDIM], g_ql[BH*SEQ*HDIM];
__device__ ushortT g_kh[BH*SEQ*HDIM], g_kl[BH*SEQ*HDIM];
__device__ ushortT g_vh[BH*SEQ*HDIM], g_vl[BH*SEQ*HDIM];
__device__ ushortT g_lnh[MROWS * DIM], g_lnl[MROWS * DIM];

// ---------------- helpers ------------------------------------------------------
__device__ __forceinline__ unsigned short b2u(__nv_bfloat16 x) {
    return *reinterpret_cast<unsigned short*>(&x);
}
__device__ __forceinline__ float u2f(unsigned short u) {
    __nv_bfloat16_raw r; r.x = u;
    __nv_bfloat16 b = r;
    return __bfloat162float(b);
}
__device__ __forceinline__ void split1(float x, unsigned short& h, unsigned short& l) {
    __nv_bfloat16 hb = __float2bfloat16_rn(x);
    float res = x - __bfloat162float(hb);
    __nv_bfloat16 lb = __float2bfloat16_rn(res);
    h = b2u(hb); l = b2u(lb);
}
__device__ __forceinline__ void splitpair(float x0, float x1, u32& h, u32& l) {
    unsigned short h0, l0, h1, l1;
    split1(x0, h0, l0); split1(x1, h1, l1);
    h = (u32)h0 | ((u32)h1 << 16);
    l = (u32)l0 | ((u32)l1 << 16);
}
__device__ __forceinline__ void mma16816(float* c, const u32* a, const u32* b) {
    asm volatile(
        "mma.sync.aligned.m16n8k16.row.col.f32.bf16.bf16.f32 "
        "{%0,%1,%2,%3}, {%4,%5,%6,%7}, {%8,%9}, {%0,%1,%2,%3};\n"
        : "+f"(c[0]), "+f"(c[1]), "+f"(c[2]), "+f"(c[3])
        : "r"(a[0]), "r"(a[1]), "r"(a[2]), "r"(a[3]), "r"(b[0]), "r"(b[1]));
}

// ---------------- small kernels -------------------------------------------------
__global__ void split_kernel(const float* __restrict__ src, ushortT* __restrict__ h,
                             ushortT* __restrict__ l, int n) {
    int i = blockIdx.x * 256 + threadIdx.x;
    if (i < n) { unsigned short hh, ll; split1(src[i], hh, ll); h[i] = hh; l[i] = ll; }
}

__global__ void make_bias3_kernel(const float* __restrict__ qb,
                                  const float* __restrict__ vb) {
    int i = blockIdx.x * 256 + threadIdx.x;
    if (i >= QKVN) return;
    float v = 0.0f;
    if (i < DIM) v = qb[i];
    else if (i >= 2*DIM) v = vb[i - 2*DIM];
    g_bias3[i] = v;
}

// ---------------- GEMM  C[M][N] = (Ah+Al)(Bh+Bl)^T + bias, bf16x3 --------------
// 128x128x32 tile, 256 threads, warp grid 4(m)x2(n), warp tile 32x64.
#define GSTR 40

__global__ __launch_bounds__(256)
void gemm_bf16x3(const ushortT* __restrict__ Ah, const ushortT* __restrict__ Al,
                 const ushortT* __restrict__ Bh, const ushortT* __restrict__ Bl,
                 const float* __restrict__ bias, float* __restrict__ C,
                 int M, int N, int K) {
    __shared__ ushortT sAh[128*GSTR], sAl[128*GSTR], sBh[128*GSTR], sBl[128*GSTR];
    const int tid = threadIdx.x;
    const int lane = tid & 31, wid = tid >> 5;
    const int wm = wid & 3, wn = wid >> 2;
    const int g = lane >> 2, t = lane & 3;
    const int m0 = blockIdx.y * 128, n0 = blockIdx.x * 128;

    float acc[2][8][4];
#pragma unroll
    for (int a = 0; a < 2; a++)
#pragma unroll
        for (int b = 0; b < 8; b++)
#pragma unroll
            for (int c = 0; c < 4; c++) acc[a][b][c] = 0.0f;

    uint4 rah[2], ral[2], rbh[2], rbl[2];

#define LOADT(KB) {                                                          \
    _Pragma("unroll")                                                        \
    for (int i = 0; i < 2; i++) {                                            \
        int sl = tid + i*256, row = sl >> 2, cg = sl & 3;                    \
        size_t oa = (size_t)(m0 + row) * K + (KB) + cg*8;                    \
        size_t ob = (size_t)(n0 + row) * K + (KB) + cg*8;                    \
        rah[i] = *(const uint4*)(Ah + oa); ral[i] = *(const uint4*)(Al + oa);\
        rbh[i] = *(const uint4*)(Bh + ob); rbl[i] = *(const uint4*)(Bl + ob);\
    } }

    LOADT(0);
    for (int kb = 0; kb < K; kb += 32) {
        __syncthreads();
#pragma unroll
        for (int i = 0; i < 2; i++) {
            int sl = tid + i*256, row = sl >> 2, cg = sl & 3;
            *(uint4*)&sAh[row*GSTR + cg*8] = rah[i];
            *(uint4*)&sAl[row*GSTR + cg*8] = ral[i];
            *(uint4*)&sBh[row*GSTR + cg*8] = rbh[i];
            *(uint4*)&sBl[row*GSTR + cg*8] = rbl[i];
        }
        __syncthreads();
        if (kb + 32 < K) LOADT(kb + 32);

#pragma unroll
        for (int kc = 0; kc < 2; kc++) {
            const int ko = kc*16 + 2*t;
            u32 ah[2][4], al[2][4];
#pragma unroll
            for (int mt = 0; mt < 2; mt++) {
                int r0 = (wm*32 + mt*16 + g) * GSTR;
                int r1 = r0 + 8*GSTR;
                ah[mt][0] = *(const u32*)&sAh[r0 + ko];
                ah[mt][1] = *(const u32*)&sAh[r1 + ko];
                ah[mt][2] = *(const u32*)&sAh[r0 + ko + 8];
                ah[mt][3] = *(const u32*)&sAh[r1 + ko + 8];
                al[mt][0] = *(const u32*)&sAl[r0 + ko];
                al[mt][1] = *(const u32*)&sAl[r1 + ko];
                al[mt][2] = *(const u32*)&sAl[r0 + ko + 8];
                al[mt][3] = *(const u32*)&sAl[r1 + ko + 8];
            }
            u32 bh_[8][2], bl_[8][2];
#pragma unroll
            for (int nt = 0; nt < 8; nt++) {
                int rb = (wn*64 + nt*8 + g) * GSTR + ko;
                bh_[nt][0] = *(const u32*)&sBh[rb];
                bh_[nt][1] = *(const u32*)&sBh[rb + 8];
                bl_[nt][0] = *(const u32*)&sBl[rb];
                bl_[nt][1] = *(const u32*)&sBl[rb + 8];
            }
#pragma unroll
            for (int mt = 0; mt < 2; mt++)
#pragma unroll
                for (int nt = 0; nt < 8; nt++) {
                    mma16816(acc[mt][nt], ah[mt], bh_[nt]);
                    mma16816(acc[mt][nt], ah[mt], bl_[nt]);
                    mma16816(acc[mt][nt], al[mt], bh_[nt]);
                }
        }
    }

#pragma unroll
    for (int mt = 0; mt < 2; mt++) {
        int mrow = m0 + wm*32 + mt*16 + g;
#pragma unroll
        for (int nt = 0; nt < 8; nt++) {
            int col = n0 + wn*64 + nt*8 + 2*t;
            float b0 = bias[col], b1 = bias[col+1];
            float2 v0 = make_float2(acc[mt][nt][0] + b0, acc[mt][nt][1] + b1);
            float2 v1 = make_float2(acc[mt][nt][2] + b0, acc[mt][nt][3] + b1);
            *(float2*)&C[(size_t)mrow * N + col] = v0;
            *(float2*)&C[(size_t)(mrow+8) * N + col] = v1;
        }
    }
#undef LOADT
}

// ---------------- QKV split + RoPE -> bf16 hi/lo pairs -------------------------
__global__ void rope_split_kernel(const float* __restrict__ pe) {
    int idx = blockIdx.x * 256 + threadIdx.x;
    int d2 = idx & 31;
    int n  = (idx >> 5) & 2047;
    int bh = idx >> 16;
    int b = bh >> 4, h = bh & 15;

    size_t src = ((size_t)(b * SEQ + n)) * QKVN + h * HDIM + d2 * 2;
    float q0 = g_qkv[src],         q1 = g_qkv[src + 1];
    float k0 = g_qkv[src + DIM],   k1 = g_qkv[src + DIM + 1];
    float v0 = g_qkv[src + 2*DIM], v1 = g_qkv[src + 2*DIM + 1];

    const float* p = &pe[((size_t)n * 32 + d2) * 4];
    float p00 = p[0], p01 = p[1], p10 = p[2], p11 = p[3];

    float Q0 = (p00*q0 + p01*q1) * 0.125f;   // fold softmax scale into q
    float Q1 = (p10*q0 + p11*q1) * 0.125f;
    float K0 = p00*k0 + p01*k1;
    float K1 = p10*k0 + p11*k1;

    size_t dst = ((size_t)bh * SEQ + n) * 32 + d2;   // u32 index (pair of bf16)
    u32 hh, ll;
    splitpair(Q0, Q1, hh, ll); ((u32*)g_qh)[dst] = hh; ((u32*)g_ql)[dst] = ll;
    splitpair(K0, K1, hh, ll); ((u32*)g_kh)[dst] = hh; ((u32*)g_kl)[dst] = ll;
    splitpair(v0, v1, hh, ll); ((u32*)g_vh)[dst] = hh; ((u32*)g_vl)[dst] = ll;
}

// ---------------- k_mean -------------------------------------------------------
__global__ void kmean_kernel(float* __restrict__ out) {
    int idx = blockIdx.x * 256 + threadIdx.x;
    int d = idx & 63;
    int n = (idx >> 6) & 2047;
    int b = idx >> 17;
    float s = 0.0f;
#pragma unroll
    for (int h = 0; h < HEADS; h++) {
        size_t o = (((size_t)(b * HEADS + h)) * SEQ + n) * HDIM + d;
        s += u2f(g_kh[o]) + u2f(g_kl[o]);
    }
    out[idx] = s * (1.0f / 16.0f);
}

// ---------------- flash attention, bf16x3 mma ----------------------------------
// block: 128 q rows (8 warps x m16), kv tiles of 64, d=64.
#define VSTR 72
__global__ __launch_bounds__(256)
void flash_bf16x3() {
    __shared__ ushortT sKh[64*VSTR], sKl[64*VSTR], sVh[64*VSTR], sVl[64*VSTR];
    const int tid = threadIdx.x, lane = tid & 31, wid = tid >> 5;
    const int g = lane >> 2, t = lane & 3;
    const int bh = blockIdx.y;
    const int q0 = blockIdx.x * 128;
    const size_t base = (size_t)bh * SEQ * HDIM;

    // Q fragments (hi/lo), rows (q0+wid*16+g, +8), held in regs
    u32 qfh[4][4], qfl[4][4];
    {
        int r0 = q0 + wid*16 + g;
        const ushortT* ph = g_qh + base + (size_t)r0 * HDIM;
        const ushortT* pl = g_ql + base + (size_t)r0 * HDIM;
#pragma unroll
        for (int c = 0; c < 4; c++) {
            int ko = c*16 + 2*t;
            qfh[c][0] = *(const u32*)(ph + ko);
            qfh[c][1] = *(const u32*)(ph + 8*HDIM + ko);
            qfh[c][2] = *(const u32*)(ph + ko + 8);
            qfh[c][3] = *(const u32*)(ph + 8*HDIM + ko + 8);
            qfl[c][0] = *(const u32*)(pl + ko);
            qfl[c][1] = *(const u32*)(pl + 8*HDIM + ko);
            qfl[c][2] = *(const u32*)(pl + ko + 8);
            qfl[c][3] = *(const u32*)(pl + 8*HDIM + ko + 8);
        }
    }

    float o[8][4];
#pragma unroll
    for (int a = 0; a < 8; a++)
#pragma unroll
        for (int b = 0; b < 4; b++) o[a][b] = 0.0f;
    float mi0 = -1e30f, mi1 = -1e30f, li0 = 0.0f, li1 = 0.0f;

    uint4 rkh[2], rkl[2], rvh[2], rvl[2];
#define LOADKV(N0) {                                                        \
    _Pragma("unroll")                                                       \
    for (int i = 0; i < 2; i++) {                                           \
        int sl = tid + i*256, row = sl >> 3, cg = sl & 7;                   \
        size_t off = base + (size_t)((N0) + row) * HDIM + cg*8;             \
        rkh[i] = *(const uint4*)(g_kh + off);                               \
        rkl[i] = *(const uint4*)(g_kl + off);                               \
        rvh[i] = *(const uint4*)(g_vh + off);                               \
        rvl[i] = *(const uint4*)(g_vl + off);                               \
    } }

    LOADKV(0);
    for (int it = 0; it < SEQ/64; it++) {
        __syncthreads();
#pragma unroll
        for (int i = 0; i < 2; i++) {
            int sl = tid + i*256, row = sl >> 3, cg = sl & 7;
            *(uint4*)&sKh[row*VSTR + cg*8] = rkh[i];
            *(uint4*)&sKl[row*VSTR + cg*8] = rkl[i];
            const ushortT* pv = (const ushortT*)&rvh[i];
            const ushortT* pw = (const ushortT*)&rvl[i];
#pragma unroll
            for (int e = 0; e < 8; e++) {
                sVh[(cg*8+e)*VSTR + row] = pv[e];   // transpose: [d][seq]
                sVl[(cg*8+e)*VSTR + row] = pw[e];
            }
        }
        __syncthreads();
        if (it + 1 < SEQ/64) LOADKV((it+1)*64);

        // S = Q K^T  (pre-scaled)
        float sc[8][4];
#pragma unroll
        for (int a = 0; a < 8; a++)
#pragma unroll
            for (int b = 0; b < 4; b++) sc[a][b] = 0.0f;
#pragma unroll
        for (int c = 0; c < 4; c++) {
            const int ko = c*16 + 2*t;
#pragma unroll
            for (int nt = 0; nt < 8; nt++) {
                int rb = (nt*8 + g)*VSTR + ko;
                u32 kb0[2] = { *(const u32*)&sKh[rb], *(const u32*)&sKh[rb + 8] };
                u32 kb1[2] = { *(const u32*)&sKl[rb], *(const u32*)&sKl[rb + 8] };
                mma16816(sc[nt], qfh[c], kb0);
                mma16816(sc[nt], qfh[c], kb1);
                mma16816(sc[nt], qfl[c], kb0);
            }
        }

        // online softmax: rows g (elems 0,1) and g+8 (elems 2,3)
        float rm0 = -1e30f, rm1 = -1e30f;
#pragma unroll
        for (int nt = 0; nt < 8; nt++) {
            rm0 = fmaxf(rm0, fmaxf(sc[nt][0], sc[nt][1]));
            rm1 = fmaxf(rm1, fmaxf(sc[nt][2], sc[nt][3]));
        }
        rm0 = fmaxf(rm0, __shfl_xor_sync(0xffffffffu, rm0, 1));
        rm0 = fmaxf(rm0, __shfl_xor_sync(0xffffffffu, rm0, 2));
        rm1 = fmaxf(rm1, __shfl_xor_sync(0xffffffffu, rm1, 1));
        rm1 = fmaxf(rm1, __shfl_xor_sync(0xffffffffu, rm1, 2));
        float mn0 = fmaxf(mi0, rm0), mn1 = fmaxf(mi1, rm1);
        float a0 = __expf(mi0 - mn0), a1 = __expf(mi1 - mn1);
        float s0 = 0.0f, s1 = 0.0f;
#pragma unroll
        for (int nt = 0; nt < 8; nt++) {
            sc[nt][0] = __expf(sc[nt][0] - mn0); s0 += sc[nt][0];
            sc[nt][1] = __expf(sc[nt][1] - mn0); s0 += sc[nt][1];
            sc[nt][2] = __expf(sc[nt][2] - mn1); s1 += sc[nt][2];
            sc[nt][3] = __expf(sc[nt][3] - mn1); s1 += sc[nt][3];
        }
        s0 += __shfl_xor_sync(0xffffffffu, s0, 1);
        s0 += __shfl_xor_sync(0xffffffffu, s0, 2);
        s1 += __shfl_xor_sync(0xffffffffu, s1, 1);
        s1 += __shfl_xor_sync(0xffffffffu, s1, 2);
        li0 = li0 * a0 + s0; li1 = li1 * a1 + s1;
        mi0 = mn0; mi1 = mn1;
#pragma unroll
        for (int nt = 0; nt < 8; nt++) {
            o[nt][0] *= a0; o[nt][1] *= a0; o[nt][2] *= a1; o[nt][3] *= a1;
        }

        // O += P V   (P split hi/lo, V split hi/lo)
#pragma unroll
        for (int j = 0; j < 4; j++) {
            u32 ph[4], pl[4];
            splitpair(sc[2*j][0],   sc[2*j][1],   ph[0], pl[0]);
            splitpair(sc[2*j][2],   sc[2*j][3],   ph[1], pl[1]);
            splitpair(sc[2*j+1][0], sc[2*j+1][1], ph[2], pl[2]);
            splitpair(sc[2*j+1][2], sc[2*j+1][3], ph[3], pl[3]);
            const int ko = j*16 + 2*t;
#pragma unroll
            for (int nt = 0; nt < 8; nt++) {
                int rb = (nt*8 + g)*VSTR + ko;
                u32 vb0[2] = { *(const u32*)&sVh[rb], *(const u32*)&sVh[rb + 8] };
                u32 vb1[2] = { *(const u32*)&sVl[rb], *(const u32*)&sVl[rb + 8] };
                mma16816(o[nt], ph, vb0);
                mma16816(o[nt], ph, vb1);
                mma16816(o[nt], pl, vb0);
            }
        }
    }

    float i0 = 1.0f / li0, i1 = 1.0f / li1;
    int r0 = q0 + wid*16 + g;
#pragma unroll
    for (int nt = 0; nt < 8; nt++) {
        int col = nt*8 + 2*t;
        float2 v0 = make_float2(o[nt][0]*i0, o[nt][1]*i0);
        float2 v1 = make_float2(o[nt][2]*i1, o[nt][3]*i1);
        *(float2*)&g_o[base + (size_t)r0 * HDIM + col] = v0;
        *(float2*)&g_o[base + (size_t)(r0+8) * HDIM + col] = v1;
    }
#undef LOADKV
}

// ---------------- LayerNorm (gather heads, write bf16 hi/lo) -------------------
__global__ __launch_bounds__(256)
void ln_kernel(const float* __restrict__ gamma, const float* __restrict__ beta) {
    int bn = blockIdx.x;
    int b = bn >> 11;
    int n = bn & 2047;

    float vals[4];
    float s = 0.0f, ss = 0.0f;
#pragma unroll
    for (int ti = 0; ti < 4; ti++) {
        int c = threadIdx.x + ti * 256;
        int h = c >> 6, d = c & 63;
        float v = g_o[(((size_t)(b * HEADS + h)) * SEQ + n) * HDIM + d];
        vals[ti] = v; s += v; ss += v * v;
    }
#pragma unroll
    for (int m = 16; m; m >>= 1) {
        s  += __shfl_xor_sync(0xffffffffu, s, m);
        ss += __shfl_xor_sync(0xffffffffu, ss, m);
    }
    __shared__ float rs[8], rss[8];
    int w = threadIdx.x >> 5, lanei = threadIdx.x & 31;
    if (lanei == 0) { rs[w] = s; rss[w] = ss; }
    __syncthreads();
    float st = 0.0f, sst = 0.0f;
#pragma unroll
    for (int i = 0; i < 8; i++) { st += rs[i]; sst += rss[i]; }

    float mean = st * (1.0f / 1024.0f);
    float var  = sst * (1.0f / 1024.0f) - mean * mean;
    float r = rsqrtf(var + 1e-5f);
#pragma unroll
    for (int ti = 0; ti < 4; ti++) {
        int c = threadIdx.x + ti * 256;
        float f = (vals[ti] - mean) * r * gamma[c] + beta[c];
        unsigned short hh, ll; split1(f, hh, ll);
        g_lnh[(size_t)bn * DIM + c] = hh;
        g_lnl[(size_t)bn * DIM + c] = ll;
    }
}

// ---------------- launch --------------------------------------------------------
extern "C" void kernel_launch(void* const* d_in, const int* in_sizes, int n_in,
                              void* d_out, int out_size) {
    const float* x      = (const float*)d_in[0];
    const float* pe     = (const float*)d_in[1];
    const float* qkv_w  = (const float*)d_in[2];
    const float* q_bias = (const float*)d_in[3];
    const float* v_bias = (const float*)d_in[4];
    const float* gamma  = (const float*)d_in[5];
    const float* beta   = (const float*)d_in[6];
    const float* proj_w = (const float*)d_in[7];
    const float* proj_b = (const float*)d_in[8];
    float* out = (float*)d_out;

    void *p_qkv, *p_bias3;
    void *p_xh, *p_xl, *p_wh, *p_wl, *p_pwh, *p_pwl, *p_lnh, *p_lnl;
    cudaGetSymbolAddress(&p_qkv, g_qkv);
    cudaGetSymbolAddress(&p_bias3, g_bias3);
    cudaGetSymbolAddress(&p_xh, g_xh);   cudaGetSymbolAddress(&p_xl, g_xl);
    cudaGetSymbolAddress(&p_wh, g_wh);   cudaGetSymbolAddress(&p_wl, g_wl);
    cudaGetSymbolAddress(&p_pwh, g_pwh); cudaGetSymbolAddress(&p_pwl, g_pwl);
    cudaGetSymbolAddress(&p_lnh, g_lnh); cudaGetSymbolAddress(&p_lnl, g_lnl);

    // 1) split inputs to bf16 hi/lo
    split_kernel<<<(MROWS*DIM + 255)/256, 256>>>(x, (ushortT*)p_xh, (ushortT*)p_xl, MROWS*DIM);
    split_kernel<<<(QKVN*DIM + 255)/256, 256>>>(qkv_w, (ushortT*)p_wh, (ushortT*)p_wl, QKVN*DIM);
    split_kernel<<<(DIM*DIM + 255)/256, 256>>>(proj_w, (ushortT*)p_pwh, (ushortT*)p_pwl, DIM*DIM);
    make_bias3_kernel<<<(QKVN + 255)/256, 256>>>(q_bias, v_bias);

    // 2) QKV GEMM (bf16x3): [4096,1024] x [3072,1024]^T
    gemm_bf16x3<<<dim3(QKVN/128, MROWS/128), 256>>>(
        (const ushortT*)p_xh, (const ushortT*)p_xl,
        (const ushortT*)p_wh, (const ushortT*)p_wl,
        (const float*)p_bias3, (float*)p_qkv, MROWS, QKVN, DIM);

    // 3) RoPE + split q/k/v (q pre-scaled by 1/8)
    rope_split_kernel<<<(BH*SEQ*32)/256, 256>>>(pe);

    // 4) k_mean side output
    kmean_kernel<<<(BATCH*SEQ*HDIM)/256, 256>>>(out + (size_t)MROWS * DIM);

    // 5) attention (bf16x3 tensor core flash)
    flash_bf16x3<<<dim3(SEQ/128, BH), 256>>>();

    // 6) layernorm (gathers heads, emits bf16 hi/lo)
    ln_kernel<<<MROWS, 256>>>(gamma, beta);

    // 7) projection GEMM (bf16x3) -> d_out
    gemm_bf16x3<<<dim3(DIM/128, MROWS/128), 256>>>(
        (const ushortT*)p_lnh, (const ushortT*)p_lnl,
        (const ushortT*)p_pwh, (const ushortT*)p_pwl,
        proj_b, out, MROWS, DIM, DIM);
}

// round 5
// speedup vs baseline: 1.9345x; 1.0414x over previous
#include <cuda_runtime.h>
#include <cuda_bf16.h>
#include <math.h>

#define BATCH 2
#define SEQ   2048
#define DIM   1024
#define HEADS 16
#define HDIM  64
#define BH    (BATCH*HEADS)          // 32
#define MROWS (BATCH*SEQ)            // 4096
#define QKVN  (3*DIM)                // 3072

typedef unsigned short ushortT;
typedef unsigned int   u32;

// ---------------- scratch (device globals) -------------------------------------
__device__ float   g_o[BH * SEQ * HDIM];
__device__ float   g_bias3[QKVN];
__device__ ushortT g_xh[MROWS * DIM],  g_xl[MROWS * DIM];
__device__ ushortT g_wh[QKVN * DIM],   g_wl[QKVN * DIM];
__device__ ushortT g_pwh[DIM * DIM],   g_pwl[DIM * DIM];
__device__ ushortT g_qh[BH*SEQ*HDIM], g_ql[BH*SEQ*HDIM];
__device__ ushortT g_kh[BH*SEQ*HDIM], g_kl[BH*SEQ*HDIM];
__device__ ushortT g_vh[BH*SEQ*HDIM], g_vl[BH*SEQ*HDIM];
__device__ ushortT g_lnh[MROWS * DIM], g_lnl[MROWS * DIM];

// ---------------- helpers ------------------------------------------------------
__device__ __forceinline__ unsigned short b2u(__nv_bfloat16 x) {
    return *reinterpret_cast<unsigned short*>(&x);
}
__device__ __forceinline__ float u2f(unsigned short u) {
    __nv_bfloat16_raw r; r.x = u;
    __nv_bfloat16 b = r;
    return __bfloat162float(b);
}
__device__ __forceinline__ void split1(float x, unsigned short& h, unsigned short& l) {
    __nv_bfloat16 hb = __float2bfloat16_rn(x);
    float res = x - __bfloat162float(hb);
    __nv_bfloat16 lb = __float2bfloat16_rn(res);
    h = b2u(hb); l = b2u(lb);
}
__device__ __forceinline__ void splitpair(float x0, float x1, u32& h, u32& l) {
    unsigned short h0, l0, h1, l1;
    split1(x0, h0, l0); split1(x1, h1, l1);
    h = (u32)h0 | ((u32)h1 << 16);
    l = (u32)l0 | ((u32)l1 << 16);
}
__device__ __forceinline__ void mma16816(float* c, const u32* a, const u32* b) {
    asm volatile(
        "mma.sync.aligned.m16n8k16.row.col.f32.bf16.bf16.f32 "
        "{%0,%1,%2,%3}, {%4,%5,%6,%7}, {%8,%9}, {%0,%1,%2,%3};\n"
        : "+f"(c[0]), "+f"(c[1]), "+f"(c[2]), "+f"(c[3])
        : "r"(a[0]), "r"(a[1]), "r"(a[2]), "r"(a[3]), "r"(b[0]), "r"(b[1]));
}
__device__ __forceinline__ u32 smem_u32(const void* p) {
    return (u32)__cvta_generic_to_shared(p);
}
__device__ __forceinline__ void cpasync16(u32 saddr, const void* g) {
    asm volatile("cp.async.cg.shared.global [%0], [%1], 16;" :: "r"(saddr), "l"(g) : "memory");
}

// ---------------- small kernels -------------------------------------------------
__global__ void split_kernel(const float* __restrict__ src, ushortT* __restrict__ h,
                             ushortT* __restrict__ l, int n) {
    int i = blockIdx.x * 256 + threadIdx.x;
    if (i < n) { unsigned short hh, ll; split1(src[i], hh, ll); h[i] = hh; l[i] = ll; }
}

__global__ void make_bias3_kernel(const float* __restrict__ qb,
                                  const float* __restrict__ vb) {
    int i = blockIdx.x * 256 + threadIdx.x;
    if (i >= QKVN) return;
    float v = 0.0f;
    if (i < DIM) v = qb[i];
    else if (i >= 2*DIM) v = vb[i - 2*DIM];
    g_bias3[i] = v;
}

// ---------------- GEMM bf16x3, 128x256 CTA, 64x64 warp tile, cp.async pipe -----
// mode 0: C[m][n] = acc + bias[n]   (fp32 out)
// mode 1: QKV epilogue: bias + RoPE + hi/lo split directly into g_q/k/v arrays.
#define BM 128
#define BN 256
#define BKS 32
#define STR 40
#define STAGE_U (BM*STR*2 + BN*STR*2)    // 30720 ushorts per stage
#define GEMM_DSMEM (2 * STAGE_U * 2)     // 122880 bytes

__global__ __launch_bounds__(256)
void gemm_bf16x3_v2(const ushortT* __restrict__ Ah, const ushortT* __restrict__ Al,
                    const ushortT* __restrict__ Bh, const ushortT* __restrict__ Bl,
                    const float* __restrict__ bias, float* __restrict__ C,
                    int M, int N, int K, int mode, const float* __restrict__ pe) {
    extern __shared__ ushortT S[];
    const int tid = threadIdx.x, lane = tid & 31, wid = tid >> 5;
    const int wm = wid >> 2, wn = wid & 3;
    const int g = lane >> 2, t = lane & 3;
    const int m0 = blockIdx.y * BM, n0 = blockIdx.x * BN;

    float acc[4][8][4];
#pragma unroll
    for (int a = 0; a < 4; a++)
#pragma unroll
        for (int b = 0; b < 8; b++)
#pragma unroll
            for (int c = 0; c < 4; c++) acc[a][b][c] = 0.0f;

#define ISSUE(SG) {                                                           \
    ushortT* st = S + ((SG) & 1) * STAGE_U;                                   \
    const int k0 = (SG) * BKS;                                                \
    _Pragma("unroll")                                                         \
    for (int i = 0; i < 2; i++) {                                             \
        int sl = tid + i*256, row = sl >> 2, cg = sl & 3;                     \
        size_t go = (size_t)(m0 + row) * K + k0 + cg*8;                       \
        cpasync16(smem_u32(st + row*STR + cg*8), Ah + go);                    \
        cpasync16(smem_u32(st + 5120 + row*STR + cg*8), Al + go);             \
    }                                                                         \
    _Pragma("unroll")                                                         \
    for (int i = 0; i < 4; i++) {                                             \
        int sl = tid + i*256, row = sl >> 2, cg = sl & 3;                     \
        size_t go = (size_t)(n0 + row) * K + k0 + cg*8;                       \
        cpasync16(smem_u32(st + 10240 + row*STR + cg*8), Bh + go);            \
        cpasync16(smem_u32(st + 20480 + row*STR + cg*8), Bl + go);            \
    }                                                                         \
    asm volatile("cp.async.commit_group;" ::: "memory");                      \
    }

    const int NS = K / BKS;
    ISSUE(0);
    for (int s = 0; s < NS; s++) {
        if (s + 1 < NS) {
            ISSUE(s + 1);
            asm volatile("cp.async.wait_group 1;" ::: "memory");
        } else {
            asm volatile("cp.async.wait_group 0;" ::: "memory");
        }
        __syncthreads();

        const ushortT* st = S + (s & 1) * STAGE_U;
        const ushortT* pAh = st;
        const ushortT* pAl = st + 5120;
        const ushortT* pBh = st + 10240;
        const ushortT* pBl = st + 20480;
#pragma unroll
        for (int kc = 0; kc < 2; kc++) {
            const int ko = kc * 16 + 2 * t;
            u32 ah[4][4], al[4][4];
#pragma unroll
            for (int mt = 0; mt < 4; mt++) {
                int r0 = (wm*64 + mt*16 + g) * STR, r1 = r0 + 8*STR;
                ah[mt][0] = *(const u32*)&pAh[r0 + ko];
                ah[mt][1] = *(const u32*)&pAh[r1 + ko];
                ah[mt][2] = *(const u32*)&pAh[r0 + ko + 8];
                ah[mt][3] = *(const u32*)&pAh[r1 + ko + 8];
                al[mt][0] = *(const u32*)&pAl[r0 + ko];
                al[mt][1] = *(const u32*)&pAl[r1 + ko];
                al[mt][2] = *(const u32*)&pAl[r0 + ko + 8];
                al[mt][3] = *(const u32*)&pAl[r1 + ko + 8];
            }
#pragma unroll
            for (int nt = 0; nt < 8; nt++) {
                int rb = (wn*64 + nt*8 + g) * STR + ko;
                u32 b0[2] = { *(const u32*)&pBh[rb], *(const u32*)&pBh[rb + 8] };
                u32 b1[2] = { *(const u32*)&pBl[rb], *(const u32*)&pBl[rb + 8] };
#pragma unroll
                for (int mt = 0; mt < 4; mt++) {
                    mma16816(acc[mt][nt], ah[mt], b0);
                    mma16816(acc[mt][nt], ah[mt], b1);
                    mma16816(acc[mt][nt], al[mt], b0);
                }
            }
        }
        __syncthreads();
    }
#undef ISSUE

    if (mode == 0) {
#pragma unroll
        for (int mt = 0; mt < 4; mt++) {
            int m = m0 + wm*64 + mt*16 + g;
#pragma unroll
            for (int nt = 0; nt < 8; nt++) {
                int c = n0 + wn*64 + nt*8 + 2*t;
                float b0 = bias[c], b1 = bias[c + 1];
                float2 v0 = make_float2(acc[mt][nt][0] + b0, acc[mt][nt][1] + b1);
                float2 v1 = make_float2(acc[mt][nt][2] + b0, acc[mt][nt][3] + b1);
                *(float2*)&C[(size_t)m * N + c] = v0;
                *(float2*)&C[(size_t)(m + 8) * N + c] = v1;
            }
        }
    } else {
        // QKV epilogue: bias + RoPE (+1/8 scale for q) + hi/lo split, scatter.
#pragma unroll
        for (int mt = 0; mt < 4; mt++) {
#pragma unroll
            for (int nt = 0; nt < 8; nt++) {
                int c = n0 + wn*64 + nt*8 + 2*t;
                float b0 = bias[c], b1 = bias[c + 1];
                int sec = c >> 10;                 // 0=q, 1=k, 2=v
                int h = (c & 1023) >> 6;
                int d2 = (c & 63) >> 1;
#pragma unroll
                for (int half = 0; half < 2; half++) {
                    int m = m0 + wm*64 + mt*16 + g + half*8;
                    int n = m & (SEQ - 1);
                    int b = m >> 11;
                    float v0 = acc[mt][nt][half*2]     + b0;
                    float v1 = acc[mt][nt][half*2 + 1] + b1;
                    float r0, r1;
                    ushortT *dh, *dl;
                    if (sec < 2) {
                        const float* p = &pe[((size_t)n * 32 + d2) * 4];
                        float p00 = p[0], p01 = p[1], p10 = p[2], p11 = p[3];
                        r0 = p00*v0 + p01*v1;
                        r1 = p10*v0 + p11*v1;
                        if (sec == 0) { r0 *= 0.125f; r1 *= 0.125f; dh = g_qh; dl = g_ql; }
                        else          { dh = g_kh; dl = g_kl; }
                    } else {
                        r0 = v0; r1 = v1; dh = g_vh; dl = g_vl;
                    }
                    size_t idx = (((size_t)(b * HEADS + h)) * SEQ + n) * 32 + d2;
                    u32 hh, ll;
                    splitpair(r0, r1, hh, ll);
                    ((u32*)dh)[idx] = hh;
                    ((u32*)dl)[idx] = ll;
                }
            }
        }
    }
}

// ---------------- k_mean -------------------------------------------------------
__global__ void kmean_kernel(float* __restrict__ out) {
    int idx = blockIdx.x * 256 + threadIdx.x;
    int d = idx & 63;
    int n = (idx >> 6) & 2047;
    int b = idx >> 17;
    float s = 0.0f;
#pragma unroll
    for (int h = 0; h < HEADS; h++) {
        size_t o = (((size_t)(b * HEADS + h)) * SEQ + n) * HDIM + d;
        s += u2f(g_kh[o]) + u2f(g_kl[o]);
    }
    out[idx] = s * (1.0f / 16.0f);
}

// ---------------- flash attention, bf16x3 mma.sync (verified, unchanged) -------
#define VSTR 72
__global__ __launch_bounds__(256)
void flash_bf16x3() {
    __shared__ ushortT sKh[64*VSTR], sKl[64*VSTR], sVh[64*VSTR], sVl[64*VSTR];
    const int tid = threadIdx.x, lane = tid & 31, wid = tid >> 5;
    const int g = lane >> 2, t = lane & 3;
    const int bh = blockIdx.y;
    const int q0 = blockIdx.x * 128;
    const size_t base = (size_t)bh * SEQ * HDIM;

    u32 qfh[4][4], qfl[4][4];
    {
        int r0 = q0 + wid*16 + g;
        const ushortT* ph = g_qh + base + (size_t)r0 * HDIM;
        const ushortT* pl = g_ql + base + (size_t)r0 * HDIM;
#pragma unroll
        for (int c = 0; c < 4; c++) {
            int ko = c*16 + 2*t;
            qfh[c][0] = *(const u32*)(ph + ko);
            qfh[c][1] = *(const u32*)(ph + 8*HDIM + ko);
            qfh[c][2] = *(const u32*)(ph + ko + 8);
            qfh[c][3] = *(const u32*)(ph + 8*HDIM + ko + 8);
            qfl[c][0] = *(const u32*)(pl + ko);
            qfl[c][1] = *(const u32*)(pl + 8*HDIM + ko);
            qfl[c][2] = *(const u32*)(pl + ko + 8);
            qfl[c][3] = *(const u32*)(pl + 8*HDIM + ko + 8);
        }
    }

    float o[8][4];
#pragma unroll
    for (int a = 0; a < 8; a++)
#pragma unroll
        for (int b = 0; b < 4; b++) o[a][b] = 0.0f;
    float mi0 = -1e30f, mi1 = -1e30f, li0 = 0.0f, li1 = 0.0f;

    uint4 rkh[2], rkl[2], rvh[2], rvl[2];
#define LOADKV(N0) {                                                        \
    _Pragma("unroll")                                                       \
    for (int i = 0; i < 2; i++) {                                           \
        int sl = tid + i*256, row = sl >> 3, cg = sl & 7;                   \
        size_t off = base + (size_t)((N0) + row) * HDIM + cg*8;             \
        rkh[i] = *(const uint4*)(g_kh + off);                               \
        rkl[i] = *(const uint4*)(g_kl + off);                               \
        rvh[i] = *(const uint4*)(g_vh + off);                               \
        rvl[i] = *(const uint4*)(g_vl + off);                               \
    } }

    LOADKV(0);
    for (int it = 0; it < SEQ/64; it++) {
        __syncthreads();
#pragma unroll
        for (int i = 0; i < 2; i++) {
            int sl = tid + i*256, row = sl >> 3, cg = sl & 7;
            *(uint4*)&sKh[row*VSTR + cg*8] = rkh[i];
            *(uint4*)&sKl[row*VSTR + cg*8] = rkl[i];
            const ushortT* pv = (const ushortT*)&rvh[i];
            const ushortT* pw = (const ushortT*)&rvl[i];
#pragma unroll
            for (int e = 0; e < 8; e++) {
                sVh[(cg*8+e)*VSTR + row] = pv[e];
                sVl[(cg*8+e)*VSTR + row] = pw[e];
            }
        }
        __syncthreads();
        if (it + 1 < SEQ/64) LOADKV((it+1)*64);

        float sc[8][4];
#pragma unroll
        for (int a = 0; a < 8; a++)
#pragma unroll
            for (int b = 0; b < 4; b++) sc[a][b] = 0.0f;
#pragma unroll
        for (int c = 0; c < 4; c++) {
            const int ko = c*16 + 2*t;
#pragma unroll
            for (int nt = 0; nt < 8; nt++) {
                int rb = (nt*8 + g)*VSTR + ko;
                u32 kb0[2] = { *(const u32*)&sKh[rb], *(const u32*)&sKh[rb + 8] };
                u32 kb1[2] = { *(const u32*)&sKl[rb], *(const u32*)&sKl[rb + 8] };
                mma16816(sc[nt], qfh[c], kb0);
                mma16816(sc[nt], qfh[c], kb1);
                mma16816(sc[nt], qfl[c], kb0);
            }
        }

        float rm0 = -1e30f, rm1 = -1e30f;
#pragma unroll
        for (int nt = 0; nt < 8; nt++) {
            rm0 = fmaxf(rm0, fmaxf(sc[nt][0], sc[nt][1]));
            rm1 = fmaxf(rm1, fmaxf(sc[nt][2], sc[nt][3]));
        }
        rm0 = fmaxf(rm0, __shfl_xor_sync(0xffffffffu, rm0, 1));
        rm0 = fmaxf(rm0, __shfl_xor_sync(0xffffffffu, rm0, 2));
        rm1 = fmaxf(rm1, __shfl_xor_sync(0xffffffffu, rm1, 1));
        rm1 = fmaxf(rm1, __shfl_xor_sync(0xffffffffu, rm1, 2));
        float mn0 = fmaxf(mi0, rm0), mn1 = fmaxf(mi1, rm1);
        float a0 = __expf(mi0 - mn0), a1 = __expf(mi1 - mn1);
        float s0 = 0.0f, s1 = 0.0f;
#pragma unroll
        for (int nt = 0; nt < 8; nt++) {
            sc[nt][0] = __expf(sc[nt][0] - mn0); s0 += sc[nt][0];
            sc[nt][1] = __expf(sc[nt][1] - mn0); s0 += sc[nt][1];
            sc[nt][2] = __expf(sc[nt][2] - mn1); s1 += sc[nt][2];
            sc[nt][3] = __expf(sc[nt][3] - mn1); s1 += sc[nt][3];
        }
        s0 += __shfl_xor_sync(0xffffffffu, s0, 1);
        s0 += __shfl_xor_sync(0xffffffffu, s0, 2);
        s1 += __shfl_xor_sync(0xffffffffu, s1, 1);
        s1 += __shfl_xor_sync(0xffffffffu, s1, 2);
        li0 = li0 * a0 + s0; li1 = li1 * a1 + s1;
        mi0 = mn0; mi1 = mn1;
#pragma unroll
        for (int nt = 0; nt < 8; nt++) {
            o[nt][0] *= a0; o[nt][1] *= a0; o[nt][2] *= a1; o[nt][3] *= a1;
        }

#pragma unroll
        for (int j = 0; j < 4; j++) {
            u32 ph[4], pl[4];
            splitpair(sc[2*j][0],   sc[2*j][1],   ph[0], pl[0]);
            splitpair(sc[2*j][2],   sc[2*j][3],   ph[1], pl[1]);
            splitpair(sc[2*j+1][0], sc[2*j+1][1], ph[2], pl[2]);
            splitpair(sc[2*j+1][2], sc[2*j+1][3], ph[3], pl[3]);
            const int ko = j*16 + 2*t;
#pragma unroll
            for (int nt = 0; nt < 8; nt++) {
                int rb = (nt*8 + g)*VSTR + ko;
                u32 vb0[2] = { *(const u32*)&sVh[rb], *(const u32*)&sVh[rb + 8] };
                u32 vb1[2] = { *(const u32*)&sVl[rb], *(const u32*)&sVl[rb + 8] };
                mma16816(o[nt], ph, vb0);
                mma16816(o[nt], ph, vb1);
                mma16816(o[nt], pl, vb0);
            }
        }
    }

    float i0 = 1.0f / li0, i1 = 1.0f / li1;
    int r0 = q0 + wid*16 + g;
#pragma unroll
    for (int nt = 0; nt < 8; nt++) {
        int col = nt*8 + 2*t;
        float2 v0 = make_float2(o[nt][0]*i0, o[nt][1]*i0);
        float2 v1 = make_float2(o[nt][2]*i1, o[nt][3]*i1);
        *(float2*)&g_o[base + (size_t)r0 * HDIM + col] = v0;
        *(float2*)&g_o[base + (size_t)(r0+8) * HDIM + col] = v1;
    }
#undef LOADKV
}

// ---------------- LayerNorm (gather heads, write bf16 hi/lo) -------------------
__global__ __launch_bounds__(256)
void ln_kernel(const float* __restrict__ gamma, const float* __restrict__ beta) {
    int bn = blockIdx.x;
    int b = bn >> 11;
    int n = bn & 2047;

    float vals[4];
    float s = 0.0f, ss = 0.0f;
#pragma unroll
    for (int ti = 0; ti < 4; ti++) {
        int c = threadIdx.x + ti * 256;
        int h = c >> 6, d = c & 63;
        float v = g_o[(((size_t)(b * HEADS + h)) * SEQ + n) * HDIM + d];
        vals[ti] = v; s += v; ss += v * v;
    }
#pragma unroll
    for (int m = 16; m; m >>= 1) {
        s  += __shfl_xor_sync(0xffffffffu, s, m);
        ss += __shfl_xor_sync(0xffffffffu, ss, m);
    }
    __shared__ float rs[8], rss[8];
    int w = threadIdx.x >> 5, lanei = threadIdx.x & 31;
    if (lanei == 0) { rs[w] = s; rss[w] = ss; }
    __syncthreads();
    float st = 0.0f, sst = 0.0f;
#pragma unroll
    for (int i = 0; i < 8; i++) { st += rs[i]; sst += rss[i]; }

    float mean = st * (1.0f / 1024.0f);
    float var  = sst * (1.0f / 1024.0f) - mean * mean;
    float r = rsqrtf(var + 1e-5f);
#pragma unroll
    for (int ti = 0; ti < 4; ti++) {
        int c = threadIdx.x + ti * 256;
        float f = (vals[ti] - mean) * r * gamma[c] + beta[c];
        unsigned short hh, ll; split1(f, hh, ll);
        g_lnh[(size_t)bn * DIM + c] = hh;
        g_lnl[(size_t)bn * DIM + c] = ll;
    }
}

// ---------------- launch --------------------------------------------------------
extern "C" void kernel_launch(void* const* d_in, const int* in_sizes, int n_in,
                              void* d_out, int out_size) {
    const float* x      = (const float*)d_in[0];
    const float* pe     = (const float*)d_in[1];
    const float* qkv_w  = (const float*)d_in[2];
    const float* q_bias = (const float*)d_in[3];
    const float* v_bias = (const float*)d_in[4];
    const float* gamma  = (const float*)d_in[5];
    const float* beta   = (const float*)d_in[6];
    const float* proj_w = (const float*)d_in[7];
    const float* proj_b = (const float*)d_in[8];
    float* out = (float*)d_out;

    void *p_bias3;
    void *p_xh, *p_xl, *p_wh, *p_wl, *p_pwh, *p_pwl, *p_lnh, *p_lnl;
    cudaGetSymbolAddress(&p_bias3, g_bias3);
    cudaGetSymbolAddress(&p_xh, g_xh);   cudaGetSymbolAddress(&p_xl, g_xl);
    cudaGetSymbolAddress(&p_wh, g_wh);   cudaGetSymbolAddress(&p_wl, g_wl);
    cudaGetSymbolAddress(&p_pwh, g_pwh); cudaGetSymbolAddress(&p_pwl, g_pwl);
    cudaGetSymbolAddress(&p_lnh, g_lnh); cudaGetSymbolAddress(&p_lnl, g_lnl);

    cudaFuncSetAttribute(gemm_bf16x3_v2,
                         cudaFuncAttributeMaxDynamicSharedMemorySize, GEMM_DSMEM);

    split_kernel<<<(MROWS*DIM + 255)/256, 256>>>(x, (ushortT*)p_xh, (ushortT*)p_xl, MROWS*DIM);
    split_kernel<<<(QKVN*DIM + 255)/256, 256>>>(qkv_w, (ushortT*)p_wh, (ushortT*)p_wl, QKVN*DIM);
    make_bias3_kernel<<<(QKVN + 255)/256, 256>>>(q_bias, v_bias);

    // QKV GEMM with fused bias + RoPE + hi/lo split epilogue
    gemm_bf16x3_v2<<<dim3(QKVN/BN, MROWS/BM), 256, GEMM_DSMEM>>>(
        (const ushortT*)p_xh, (const ushortT*)p_xl,
        (const ushortT*)p_wh, (const ushortT*)p_wl,
        (const float*)p_bias3, nullptr, MROWS, QKVN, DIM, 1, pe);

    split_kernel<<<(DIM*DIM + 255)/256, 256>>>(proj_w, (ushortT*)p_pwh, (ushortT*)p_pwl, DIM*DIM);
    kmean_kernel<<<(BATCH*SEQ*HDIM)/256, 256>>>(out + (size_t)MROWS * DIM);
    flash_bf16x3<<<dim3(SEQ/128, BH), 256>>>();
    ln_kernel<<<MROWS, 256>>>(gamma, beta);

    // projection GEMM -> d_out
    gemm_bf16x3_v2<<<dim3(DIM/BN, MROWS/BM), 256, GEMM_DSMEM>>>(
        (const ushortT*)p_lnh, (const ushortT*)p_lnl,
        (const ushortT*)p_pwh, (const ushortT*)p_pwl,
        proj_b, out, MROWS, DIM, DIM, 0, nullptr);
}

// round 6
// speedup vs baseline: 2.0370x; 1.0529x over previous
#include <cuda_runtime.h>
#include <cuda_bf16.h>
#include <math.h>

#define BATCH 2
#define SEQ   2048
#define DIM   1024
#define HEADS 16
#define HDIM  64
#define BH    (BATCH*HEADS)          // 32
#define MROWS (BATCH*SEQ)            // 4096
#define QKVN  (3*DIM)                // 3072

typedef unsigned short ushortT;
typedef unsigned int   u32;

// ---------------- scratch (device globals) -------------------------------------
__device__ float   g_o[BH * SEQ * HDIM];
__device__ float   g_bias3[QKVN];
__device__ ushortT g_xh[MROWS * DIM],  g_xl[MROWS * DIM];
__device__ ushortT g_wh[QKVN * DIM],   g_wl[QKVN * DIM];
__device__ ushortT g_pwh[DIM * DIM],   g_pwl[DIM * DIM];
__device__ ushortT g_qh[BH*SEQ*HDIM], g_ql[BH*SEQ*HDIM];
__device__ ushortT g_kh[BH*SEQ*HDIM], g_kl[BH*SEQ*HDIM];
__device__ ushortT g_vh[BH*SEQ*HDIM], g_vl[BH*SEQ*HDIM];
__device__ ushortT g_lnh[MROWS * DIM], g_lnl[MROWS * DIM];

// ---------------- helpers ------------------------------------------------------
__device__ __forceinline__ unsigned short b2u(__nv_bfloat16 x) {
    return *reinterpret_cast<unsigned short*>(&x);
}
__device__ __forceinline__ float u2f(unsigned short u) {
    __nv_bfloat16_raw r; r.x = u;
    __nv_bfloat16 b = r;
    return __bfloat162float(b);
}
__device__ __forceinline__ void split1(float x, unsigned short& h, unsigned short& l) {
    __nv_bfloat16 hb = __float2bfloat16_rn(x);
    float res = x - __bfloat162float(hb);
    __nv_bfloat16 lb = __float2bfloat16_rn(res);
    h = b2u(hb); l = b2u(lb);
}
__device__ __forceinline__ void splitpair(float x0, float x1, u32& h, u32& l) {
    unsigned short h0, l0, h1, l1;
    split1(x0, h0, l0); split1(x1, h1, l1);
    h = (u32)h0 | ((u32)h1 << 16);
    l = (u32)l0 | ((u32)l1 << 16);
}
__device__ __forceinline__ void mma16816(float* c, const u32* a, const u32* b) {
    asm volatile(
        "mma.sync.aligned.m16n8k16.row.col.f32.bf16.bf16.f32 "
        "{%0,%1,%2,%3}, {%4,%5,%6,%7}, {%8,%9}, {%0,%1,%2,%3};\n"
        : "+f"(c[0]), "+f"(c[1]), "+f"(c[2]), "+f"(c[3])
        : "r"(a[0]), "r"(a[1]), "r"(a[2]), "r"(a[3]), "r"(b[0]), "r"(b[1]));
}
__device__ __forceinline__ u32 smem_u32(const void* p) {
    return (u32)__cvta_generic_to_shared(p);
}
__device__ __forceinline__ void cpasync16(u32 saddr, const void* g) {
    asm volatile("cp.async.cg.shared.global [%0], [%1], 16;" :: "r"(saddr), "l"(g) : "memory");
}

// ---------------- small kernels -------------------------------------------------
__global__ void split_kernel(const float* __restrict__ src, ushortT* __restrict__ h,
                             ushortT* __restrict__ l, int n) {
    int i = blockIdx.x * 256 + threadIdx.x;
    if (i < n) { unsigned short hh, ll; split1(src[i], hh, ll); h[i] = hh; l[i] = ll; }
}

__global__ void make_bias3_kernel(const float* __restrict__ qb,
                                  const float* __restrict__ vb) {
    int i = blockIdx.x * 256 + threadIdx.x;
    if (i >= QKVN) return;
    float v = 0.0f;
    if (i < DIM) v = qb[i];
    else if (i >= 2*DIM) v = vb[i - 2*DIM];
    g_bias3[i] = v;
}

// ---------------- GEMM bf16x3, 128x128 CTA, 64x32 warp tile, 2 CTAs/SM ---------
// mode 0: C[m][n] = acc + bias[n]   (fp32 out)
// mode 1: QKV epilogue: bias + RoPE + hi/lo split directly into g_q/k/v arrays.
#define BM 128
#define BN 128
#define BKS 32
#define STR 40
#define ARR_U (BM * STR)                 // 5120 ushorts per sub-array
#define STAGE_U (4 * ARR_U)              // 20480 ushorts per stage
#define GEMM_DSMEM (2 * STAGE_U * 2)     // 81920 bytes

__global__ __launch_bounds__(256, 2)
void gemm_bf16x3_v3(const ushortT* __restrict__ Ah, const ushortT* __restrict__ Al,
                    const ushortT* __restrict__ Bh, const ushortT* __restrict__ Bl,
                    const float* __restrict__ bias, float* __restrict__ C,
                    int M, int N, int K, int mode, const float* __restrict__ pe) {
    extern __shared__ ushortT S[];
    const int tid = threadIdx.x, lane = tid & 31, wid = tid >> 5;
    const int wm = wid >> 2, wn = wid & 3;       // 2 x 4 warp grid
    const int g = lane >> 2, t = lane & 3;
    const int m0 = blockIdx.y * BM, n0 = blockIdx.x * BN;

    float acc[4][4][4];                          // [mt][nt][4]
#pragma unroll
    for (int a = 0; a < 4; a++)
#pragma unroll
        for (int b = 0; b < 4; b++)
#pragma unroll
            for (int c = 0; c < 4; c++) acc[a][b][c] = 0.0f;

#define ISSUE(SG) {                                                           \
    ushortT* st = S + ((SG) & 1) * STAGE_U;                                   \
    const int k0 = (SG) * BKS;                                                \
    _Pragma("unroll")                                                         \
    for (int i = 0; i < 2; i++) {                                             \
        int sl = tid + i*256, row = sl >> 2, cg = sl & 3;                     \
        size_t ga = (size_t)(m0 + row) * K + k0 + cg*8;                       \
        size_t gb = (size_t)(n0 + row) * K + k0 + cg*8;                       \
        u32 so = (u32)(row*STR + cg*8);                                       \
        cpasync16(smem_u32(st) + so*2, Ah + ga);                              \
        cpasync16(smem_u32(st + ARR_U) + so*2, Al + ga);                      \
        cpasync16(smem_u32(st + 2*ARR_U) + so*2, Bh + gb);                    \
        cpasync16(smem_u32(st + 3*ARR_U) + so*2, Bl + gb);                    \
    }                                                                         \
    asm volatile("cp.async.commit_group;" ::: "memory");                      \
    }

    const int NS = K / BKS;
    ISSUE(0);
    for (int s = 0; s < NS; s++) {
        if (s + 1 < NS) {
            ISSUE(s + 1);
            asm volatile("cp.async.wait_group 1;" ::: "memory");
        } else {
            asm volatile("cp.async.wait_group 0;" ::: "memory");
        }
        __syncthreads();

        const ushortT* st = S + (s & 1) * STAGE_U;
        const ushortT* pAh = st;
        const ushortT* pAl = st + ARR_U;
        const ushortT* pBh = st + 2*ARR_U;
        const ushortT* pBl = st + 3*ARR_U;
#pragma unroll
        for (int kc = 0; kc < 2; kc++) {
            const int ko = kc * 16 + 2 * t;
            u32 bh_[4][2], bl_[4][2];
#pragma unroll
            for (int nt = 0; nt < 4; nt++) {
                int rb = (wn*32 + nt*8 + g) * STR + ko;
                bh_[nt][0] = *(const u32*)&pBh[rb];
                bh_[nt][1] = *(const u32*)&pBh[rb + 8];
                bl_[nt][0] = *(const u32*)&pBl[rb];
                bl_[nt][1] = *(const u32*)&pBl[rb + 8];
            }
#pragma unroll
            for (int mt = 0; mt < 4; mt++) {
                int r0 = (wm*64 + mt*16 + g) * STR, r1 = r0 + 8*STR;
                u32 ah[4], al[4];
                ah[0] = *(const u32*)&pAh[r0 + ko];
                ah[1] = *(const u32*)&pAh[r1 + ko];
                ah[2] = *(const u32*)&pAh[r0 + ko + 8];
                ah[3] = *(const u32*)&pAh[r1 + ko + 8];
                al[0] = *(const u32*)&pAl[r0 + ko];
                al[1] = *(const u32*)&pAl[r1 + ko];
                al[2] = *(const u32*)&pAl[r0 + ko + 8];
                al[3] = *(const u32*)&pAl[r1 + ko + 8];
#pragma unroll
                for (int nt = 0; nt < 4; nt++) {
                    mma16816(acc[mt][nt], ah, bh_[nt]);
                    mma16816(acc[mt][nt], ah, bl_[nt]);
                    mma16816(acc[mt][nt], al, bh_[nt]);
                }
            }
        }
        __syncthreads();
    }
#undef ISSUE

    if (mode == 0) {
#pragma unroll
        for (int mt = 0; mt < 4; mt++) {
            int m = m0 + wm*64 + mt*16 + g;
#pragma unroll
            for (int nt = 0; nt < 4; nt++) {
                int c = n0 + wn*32 + nt*8 + 2*t;
                float b0 = bias[c], b1 = bias[c + 1];
                float2 v0 = make_float2(acc[mt][nt][0] + b0, acc[mt][nt][1] + b1);
                float2 v1 = make_float2(acc[mt][nt][2] + b0, acc[mt][nt][3] + b1);
                *(float2*)&C[(size_t)m * N + c] = v0;
                *(float2*)&C[(size_t)(m + 8) * N + c] = v1;
            }
        }
    } else {
        // QKV epilogue: bias + RoPE (+1/8 scale for q) + hi/lo split, scatter.
#pragma unroll
        for (int mt = 0; mt < 4; mt++) {
#pragma unroll
            for (int nt = 0; nt < 4; nt++) {
                int c = n0 + wn*32 + nt*8 + 2*t;
                float b0 = bias[c], b1 = bias[c + 1];
                int sec = c >> 10;                 // 0=q, 1=k, 2=v
                int h = (c & 1023) >> 6;
                int d2 = (c & 63) >> 1;
#pragma unroll
                for (int half = 0; half < 2; half++) {
                    int m = m0 + wm*64 + mt*16 + g + half*8;
                    int n = m & (SEQ - 1);
                    int b = m >> 11;
                    float v0 = acc[mt][nt][half*2]     + b0;
                    float v1 = acc[mt][nt][half*2 + 1] + b1;
                    float r0, r1;
                    ushortT *dh, *dl;
                    if (sec < 2) {
                        const float* p = &pe[((size_t)n * 32 + d2) * 4];
                        float p00 = p[0], p01 = p[1], p10 = p[2], p11 = p[3];
                        r0 = p00*v0 + p01*v1;
                        r1 = p10*v0 + p11*v1;
                        if (sec == 0) { r0 *= 0.125f; r1 *= 0.125f; dh = g_qh; dl = g_ql; }
                        else          { dh = g_kh; dl = g_kl; }
                    } else {
                        r0 = v0; r1 = v1; dh = g_vh; dl = g_vl;
                    }
                    size_t idx = (((size_t)(b * HEADS + h)) * SEQ + n) * 32 + d2;
                    u32 hh, ll;
                    splitpair(r0, r1, hh, ll);
                    ((u32*)dh)[idx] = hh;
                    ((u32*)dl)[idx] = ll;
                }
            }
        }
    }
}

// ---------------- k_mean -------------------------------------------------------
__global__ void kmean_kernel(float* __restrict__ out) {
    int idx = blockIdx.x * 256 + threadIdx.x;
    int d = idx & 63;
    int n = (idx >> 6) & 2047;
    int b = idx >> 17;
    float s = 0.0f;
#pragma unroll
    for (int h = 0; h < HEADS; h++) {
        size_t o = (((size_t)(b * HEADS + h)) * SEQ + n) * HDIM + d;
        s += u2f(g_kh[o]) + u2f(g_kl[o]);
    }
    out[idx] = s * (1.0f / 16.0f);
}

// ---------------- flash attention, bf16x3 mma.sync (verified, unchanged) -------
#define VSTR 72
__global__ __launch_bounds__(256)
void flash_bf16x3() {
    __shared__ ushortT sKh[64*VSTR], sKl[64*VSTR], sVh[64*VSTR], sVl[64*VSTR];
    const int tid = threadIdx.x, lane = tid & 31, wid = tid >> 5;
    const int g = lane >> 2, t = lane & 3;
    const int bh = blockIdx.y;
    const int q0 = blockIdx.x * 128;
    const size_t base = (size_t)bh * SEQ * HDIM;

    u32 qfh[4][4], qfl[4][4];
    {
        int r0 = q0 + wid*16 + g;
        const ushortT* ph = g_qh + base + (size_t)r0 * HDIM;
        const ushortT* pl = g_ql + base + (size_t)r0 * HDIM;
#pragma unroll
        for (int c = 0; c < 4; c++) {
            int ko = c*16 + 2*t;
            qfh[c][0] = *(const u32*)(ph + ko);
            qfh[c][1] = *(const u32*)(ph + 8*HDIM + ko);
            qfh[c][2] = *(const u32*)(ph + ko + 8);
            qfh[c][3] = *(const u32*)(ph + 8*HDIM + ko + 8);
            qfl[c][0] = *(const u32*)(pl + ko);
            qfl[c][1] = *(const u32*)(pl + 8*HDIM + ko);
            qfl[c][2] = *(const u32*)(pl + ko + 8);
            qfl[c][3] = *(const u32*)(pl + 8*HDIM + ko + 8);
        }
    }

    float o[8][4];
#pragma unroll
    for (int a = 0; a < 8; a++)
#pragma unroll
        for (int b = 0; b < 4; b++) o[a][b] = 0.0f;
    float mi0 = -1e30f, mi1 = -1e30f, li0 = 0.0f, li1 = 0.0f;

    uint4 rkh[2], rkl[2], rvh[2], rvl[2];
#define LOADKV(N0) {                                                        \
    _Pragma("unroll")                                                       \
    for (int i = 0; i < 2; i++) {                                           \
        int sl = tid + i*256, row = sl >> 3, cg = sl & 7;                   \
        size_t off = base + (size_t)((N0) + row) * HDIM + cg*8;             \
        rkh[i] = *(const uint4*)(g_kh + off);                               \
        rkl[i] = *(const uint4*)(g_kl + off);                               \
        rvh[i] = *(const uint4*)(g_vh + off);                               \
        rvl[i] = *(const uint4*)(g_vl + off);                               \
    } }

    LOADKV(0);
    for (int it = 0; it < SEQ/64; it++) {
        __syncthreads();
#pragma unroll
        for (int i = 0; i < 2; i++) {
            int sl = tid + i*256, row = sl >> 3, cg = sl & 7;
            *(uint4*)&sKh[row*VSTR + cg*8] = rkh[i];
            *(uint4*)&sKl[row*VSTR + cg*8] = rkl[i];
            const ushortT* pv = (const ushortT*)&rvh[i];
            const ushortT* pw = (const ushortT*)&rvl[i];
#pragma unroll
            for (int e = 0; e < 8; e++) {
                sVh[(cg*8+e)*VSTR + row] = pv[e];
                sVl[(cg*8+e)*VSTR + row] = pw[e];
            }
        }
        __syncthreads();
        if (it + 1 < SEQ/64) LOADKV((it+1)*64);

        float sc[8][4];
#pragma unroll
        for (int a = 0; a < 8; a++)
#pragma unroll
            for (int b = 0; b < 4; b++) sc[a][b] = 0.0f;
#pragma unroll
        for (int c = 0; c < 4; c++) {
            const int ko = c*16 + 2*t;
#pragma unroll
            for (int nt = 0; nt < 8; nt++) {
                int rb = (nt*8 + g)*VSTR + ko;
                u32 kb0[2] = { *(const u32*)&sKh[rb], *(const u32*)&sKh[rb + 8] };
                u32 kb1[2] = { *(const u32*)&sKl[rb], *(const u32*)&sKl[rb + 8] };
                mma16816(sc[nt], qfh[c], kb0);
                mma16816(sc[nt], qfh[c], kb1);
                mma16816(sc[nt], qfl[c], kb0);
            }
        }

        float rm0 = -1e30f, rm1 = -1e30f;
#pragma unroll
        for (int nt = 0; nt < 8; nt++) {
            rm0 = fmaxf(rm0, fmaxf(sc[nt][0], sc[nt][1]));
            rm1 = fmaxf(rm1, fmaxf(sc[nt][2], sc[nt][3]));
        }
        rm0 = fmaxf(rm0, __shfl_xor_sync(0xffffffffu, rm0, 1));
        rm0 = fmaxf(rm0, __shfl_xor_sync(0xffffffffu, rm0, 2));
        rm1 = fmaxf(rm1, __shfl_xor_sync(0xffffffffu, rm1, 1));
        rm1 = fmaxf(rm1, __shfl_xor_sync(0xffffffffu, rm1, 2));
        float mn0 = fmaxf(mi0, rm0), mn1 = fmaxf(mi1, rm1);
        float a0 = __expf(mi0 - mn0), a1 = __expf(mi1 - mn1);
        float s0 = 0.0f, s1 = 0.0f;
#pragma unroll
        for (int nt = 0; nt < 8; nt++) {
            sc[nt][0] = __expf(sc[nt][0] - mn0); s0 += sc[nt][0];
            sc[nt][1] = __expf(sc[nt][1] - mn0); s0 += sc[nt][1];
            sc[nt][2] = __expf(sc[nt][2] - mn1); s1 += sc[nt][2];
            sc[nt][3] = __expf(sc[nt][3] - mn1); s1 += sc[nt][3];
        }
        s0 += __shfl_xor_sync(0xffffffffu, s0, 1);
        s0 += __shfl_xor_sync(0xffffffffu, s0, 2);
        s1 += __shfl_xor_sync(0xffffffffu, s1, 1);
        s1 += __shfl_xor_sync(0xffffffffu, s1, 2);
        li0 = li0 * a0 + s0; li1 = li1 * a1 + s1;
        mi0 = mn0; mi1 = mn1;
#pragma unroll
        for (int nt = 0; nt < 8; nt++) {
            o[nt][0] *= a0; o[nt][1] *= a0; o[nt][2] *= a1; o[nt][3] *= a1;
        }

#pragma unroll
        for (int j = 0; j < 4; j++) {
            u32 ph[4], pl[4];
            splitpair(sc[2*j][0],   sc[2*j][1],   ph[0], pl[0]);
            splitpair(sc[2*j][2],   sc[2*j][3],   ph[1], pl[1]);
            splitpair(sc[2*j+1][0], sc[2*j+1][1], ph[2], pl[2]);
            splitpair(sc[2*j+1][2], sc[2*j+1][3], ph[3], pl[3]);
            const int ko = j*16 + 2*t;
#pragma unroll
            for (int nt = 0; nt < 8; nt++) {
                int rb = (nt*8 + g)*VSTR + ko;
                u32 vb0[2] = { *(const u32*)&sVh[rb], *(const u32*)&sVh[rb + 8] };
                u32 vb1[2] = { *(const u32*)&sVl[rb], *(const u32*)&sVl[rb + 8] };
                mma16816(o[nt], ph, vb0);
                mma16816(o[nt], ph, vb1);
                mma16816(o[nt], pl, vb0);
            }
        }
    }

    float i0 = 1.0f / li0, i1 = 1.0f / li1;
    int r0 = q0 + wid*16 + g;
#pragma unroll
    for (int nt = 0; nt < 8; nt++) {
        int col = nt*8 + 2*t;
        float2 v0 = make_float2(o[nt][0]*i0, o[nt][1]*i0);
        float2 v1 = make_float2(o[nt][2]*i1, o[nt][3]*i1);
        *(float2*)&g_o[base + (size_t)r0 * HDIM + col] = v0;
        *(float2*)&g_o[base + (size_t)(r0+8) * HDIM + col] = v1;
    }
#undef LOADKV
}

// ---------------- LayerNorm (gather heads, write bf16 hi/lo) -------------------
__global__ __launch_bounds__(256)
void ln_kernel(const float* __restrict__ gamma, const float* __restrict__ beta) {
    int bn = blockIdx.x;
    int b = bn >> 11;
    int n = bn & 2047;

    float vals[4];
    float s = 0.0f, ss = 0.0f;
#pragma unroll
    for (int ti = 0; ti < 4; ti++) {
        int c = threadIdx.x + ti * 256;
        int h = c >> 6, d = c & 63;
        float v = g_o[(((size_t)(b * HEADS + h)) * SEQ + n) * HDIM + d];
        vals[ti] = v; s += v; ss += v * v;
    }
#pragma unroll
    for (int m = 16; m; m >>= 1) {
        s  += __shfl_xor_sync(0xffffffffu, s, m);
        ss += __shfl_xor_sync(0xffffffffu, ss, m);
    }
    __shared__ float rs[8], rss[8];
    int w = threadIdx.x >> 5, lanei = threadIdx.x & 31;
    if (lanei == 0) { rs[w] = s; rss[w] = ss; }
    __syncthreads();
    float st = 0.0f, sst = 0.0f;
#pragma unroll
    for (int i = 0; i < 8; i++) { st += rs[i]; sst += rss[i]; }

    float mean = st * (1.0f / 1024.0f);
    float var  = sst * (1.0f / 1024.0f) - mean * mean;
    float r = rsqrtf(var + 1e-5f);
#pragma unroll
    for (int ti = 0; ti < 4; ti++) {
        int c = threadIdx.x + ti * 256;
        float f = (vals[ti] - mean) * r * gamma[c] + beta[c];
        unsigned short hh, ll; split1(f, hh, ll);
        g_lnh[(size_t)bn * DIM + c] = hh;
        g_lnl[(size_t)bn * DIM + c] = ll;
    }
}

// ---------------- launch --------------------------------------------------------
extern "C" void kernel_launch(void* const* d_in, const int* in_sizes, int n_in,
                              void* d_out, int out_size) {
    const float* x      = (const float*)d_in[0];
    const float* pe     = (const float*)d_in[1];
    const float* qkv_w  = (const float*)d_in[2];
    const float* q_bias = (const float*)d_in[3];
    const float* v_bias = (const float*)d_in[4];
    const float* gamma  = (const float*)d_in[5];
    const float* beta   = (const float*)d_in[6];
    const float* proj_w = (const float*)d_in[7];
    const float* proj_b = (const float*)d_in[8];
    float* out = (float*)d_out;

    void *p_bias3;
    void *p_xh, *p_xl, *p_wh, *p_wl, *p_pwh, *p_pwl, *p_lnh, *p_lnl;
    cudaGetSymbolAddress(&p_bias3, g_bias3);
    cudaGetSymbolAddress(&p_xh, g_xh);   cudaGetSymbolAddress(&p_xl, g_xl);
    cudaGetSymbolAddress(&p_wh, g_wh);   cudaGetSymbolAddress(&p_wl, g_wl);
    cudaGetSymbolAddress(&p_pwh, g_pwh); cudaGetSymbolAddress(&p_pwl, g_pwl);
    cudaGetSymbolAddress(&p_lnh, g_lnh); cudaGetSymbolAddress(&p_lnl, g_lnl);

    cudaFuncSetAttribute(gemm_bf16x3_v3,
                         cudaFuncAttributeMaxDynamicSharedMemorySize, GEMM_DSMEM);

    split_kernel<<<(MROWS*DIM + 255)/256, 256>>>(x, (ushortT*)p_xh, (ushortT*)p_xl, MROWS*DIM);
    split_kernel<<<(QKVN*DIM + 255)/256, 256>>>(qkv_w, (ushortT*)p_wh, (ushortT*)p_wl, QKVN*DIM);
    make_bias3_kernel<<<(QKVN + 255)/256, 256>>>(q_bias, v_bias);

    // QKV GEMM with fused bias + RoPE + hi/lo split epilogue
    gemm_bf16x3_v3<<<dim3(QKVN/BN, MROWS/BM), 256, GEMM_DSMEM>>>(
        (const ushortT*)p_xh, (const ushortT*)p_xl,
        (const ushortT*)p_wh, (const ushortT*)p_wl,
        (const float*)p_bias3, nullptr, MROWS, QKVN, DIM, 1, pe);

    split_kernel<<<(DIM*DIM + 255)/256, 256>>>(proj_w, (ushortT*)p_pwh, (ushortT*)p_pwl, DIM*DIM);
    kmean_kernel<<<(BATCH*SEQ*HDIM)/256, 256>>>(out + (size_t)MROWS * DIM);
    flash_bf16x3<<<dim3(SEQ/128, BH), 256>>>();
    ln_kernel<<<MROWS, 256>>>(gamma, beta);

    // projection GEMM -> d_out
    gemm_bf16x3_v3<<<dim3(DIM/BN, MROWS/BM), 256, GEMM_DSMEM>>>(
        (const ushortT*)p_lnh, (const ushortT*)p_lnl,
        (const ushortT*)p_pwh, (const ushortT*)p_pwl,
        proj_b, out, MROWS, DIM, DIM, 0, nullptr);
}

// round 7
// speedup vs baseline: 2.0878x; 1.0249x over previous
#include <cuda_runtime.h>
#include <cuda_bf16.h>
#include <math.h>

#define BATCH 2
#define SEQ   2048
#define DIM   1024
#define HEADS 16
#define HDIM  64
#define BH    (BATCH*HEADS)          // 32
#define MROWS (BATCH*SEQ)            // 4096
#define QKVN  (3*DIM)                // 3072

typedef unsigned short ushortT;
typedef unsigned int   u32;

// ---------------- scratch (device globals) -------------------------------------
__device__ float   g_o[BH * SEQ * HDIM];
__device__ float   g_bias3[QKVN];
__device__ ushortT g_xh[MROWS * DIM],  g_xl[MROWS * DIM];
__device__ ushortT g_wh[QKVN * DIM],   g_wl[QKVN * DIM];
__device__ ushortT g_pwh[DIM * DIM],   g_pwl[DIM * DIM];
__device__ ushortT g_qh[BH*SEQ*HDIM], g_ql[BH*SEQ*HDIM];
__device__ ushortT g_kh[BH*SEQ*HDIM], g_kl[BH*SEQ*HDIM];
__device__ ushortT g_vh[BH*SEQ*HDIM], g_vl[BH*SEQ*HDIM];
__device__ ushortT g_lnh[MROWS * DIM], g_lnl[MROWS * DIM];

// ---------------- helpers ------------------------------------------------------
__device__ __forceinline__ unsigned short b2u(__nv_bfloat16 x) {
    return *reinterpret_cast<unsigned short*>(&x);
}
__device__ __forceinline__ float u2f(unsigned short u) {
    __nv_bfloat16_raw r; r.x = u;
    __nv_bfloat16 b = r;
    return __bfloat162float(b);
}
__device__ __forceinline__ void split1(float x, unsigned short& h, unsigned short& l) {
    __nv_bfloat16 hb = __float2bfloat16_rn(x);
    float res = x - __bfloat162float(hb);
    __nv_bfloat16 lb = __float2bfloat16_rn(res);
    h = b2u(hb); l = b2u(lb);
}
__device__ __forceinline__ void splitpair(float x0, float x1, u32& h, u32& l) {
    unsigned short h0, l0, h1, l1;
    split1(x0, h0, l0); split1(x1, h1, l1);
    h = (u32)h0 | ((u32)h1 << 16);
    l = (u32)l0 | ((u32)l1 << 16);
}
__device__ __forceinline__ void mma16816(float* c, const u32* a, const u32* b) {
    asm volatile(
        "mma.sync.aligned.m16n8k16.row.col.f32.bf16.bf16.f32 "
        "{%0,%1,%2,%3}, {%4,%5,%6,%7}, {%8,%9}, {%0,%1,%2,%3};\n"
        : "+f"(c[0]), "+f"(c[1]), "+f"(c[2]), "+f"(c[3])
        : "r"(a[0]), "r"(a[1]), "r"(a[2]), "r"(a[3]), "r"(b[0]), "r"(b[1]));
}
__device__ __forceinline__ u32 smem_u32(const void* p) {
    return (u32)__cvta_generic_to_shared(p);
}
__device__ __forceinline__ void cpasync16(u32 saddr, const void* g) {
    asm volatile("cp.async.cg.shared.global [%0], [%1], 16;" :: "r"(saddr), "l"(g) : "memory");
}

// ---------------- small kernels -------------------------------------------------
__global__ void split_kernel(const float* __restrict__ src, ushortT* __restrict__ h,
                             ushortT* __restrict__ l, int n) {
    int i = blockIdx.x * 256 + threadIdx.x;
    if (i < n) { unsigned short hh, ll; split1(src[i], hh, ll); h[i] = hh; l[i] = ll; }
}

__global__ void make_bias3_kernel(const float* __restrict__ qb,
                                  const float* __restrict__ vb) {
    int i = blockIdx.x * 256 + threadIdx.x;
    if (i >= QKVN) return;
    float v = 0.0f;
    if (i < DIM) v = qb[i];
    else if (i >= 2*DIM) v = vb[i - 2*DIM];
    g_bias3[i] = v;
}

// ---------------- GEMM bf16x3, 128x128 CTA, 64x32 warp tile, 2 CTAs/SM ---------
// mma emission is pass-major: all (Ah*Bh) across nt, then (Ah*Bl), then (Al*Bh)
// so same-accumulator mmas are 4 issue slots apart (breaks RAW chains).
#define BM 128
#define BN 128
#define BKS 32
#define STR 40
#define ARR_U (BM * STR)                 // 5120 ushorts per sub-array
#define STAGE_U (4 * ARR_U)              // 20480 ushorts per stage
#define GEMM_DSMEM (2 * STAGE_U * 2)     // 81920 bytes

__global__ __launch_bounds__(256, 2)
void gemm_bf16x3_v4(const ushortT* __restrict__ Ah, const ushortT* __restrict__ Al,
                    const ushortT* __restrict__ Bh, const ushortT* __restrict__ Bl,
                    const float* __restrict__ bias, float* __restrict__ C,
                    int M, int N, int K, int mode, const float* __restrict__ pe) {
    extern __shared__ ushortT S[];
    const int tid = threadIdx.x, lane = tid & 31, wid = tid >> 5;
    const int wm = wid >> 2, wn = wid & 3;       // 2 x 4 warp grid
    const int g = lane >> 2, t = lane & 3;
    const int m0 = blockIdx.y * BM, n0 = blockIdx.x * BN;

    float acc[4][4][4];                          // [mt][nt][4]
#pragma unroll
    for (int a = 0; a < 4; a++)
#pragma unroll
        for (int b = 0; b < 4; b++)
#pragma unroll
            for (int c = 0; c < 4; c++) acc[a][b][c] = 0.0f;

#define ISSUE(SG) {                                                           \
    ushortT* st = S + ((SG) & 1) * STAGE_U;                                   \
    const int k0 = (SG) * BKS;                                                \
    _Pragma("unroll")                                                         \
    for (int i = 0; i < 2; i++) {                                             \
        int sl = tid + i*256, row = sl >> 2, cg = sl & 3;                     \
        size_t ga = (size_t)(m0 + row) * K + k0 + cg*8;                       \
        size_t gb = (size_t)(n0 + row) * K + k0 + cg*8;                       \
        u32 so = (u32)(row*STR + cg*8);                                       \
        cpasync16(smem_u32(st) + so*2, Ah + ga);                              \
        cpasync16(smem_u32(st + ARR_U) + so*2, Al + ga);                      \
        cpasync16(smem_u32(st + 2*ARR_U) + so*2, Bh + gb);                    \
        cpasync16(smem_u32(st + 3*ARR_U) + so*2, Bl + gb);                    \
    }                                                                         \
    asm volatile("cp.async.commit_group;" ::: "memory");                      \
    }

    const int NS = K / BKS;
    ISSUE(0);
    for (int s = 0; s < NS; s++) {
        if (s + 1 < NS) {
            ISSUE(s + 1);
            asm volatile("cp.async.wait_group 1;" ::: "memory");
        } else {
            asm volatile("cp.async.wait_group 0;" ::: "memory");
        }
        __syncthreads();

        const ushortT* st = S + (s & 1) * STAGE_U;
        const ushortT* pAh = st;
        const ushortT* pAl = st + ARR_U;
        const ushortT* pBh = st + 2*ARR_U;
        const ushortT* pBl = st + 3*ARR_U;
#pragma unroll
        for (int kc = 0; kc < 2; kc++) {
            const int ko = kc * 16 + 2 * t;
            u32 bh_[4][2], bl_[4][2];
#pragma unroll
            for (int nt = 0; nt < 4; nt++) {
                int rb = (wn*32 + nt*8 + g) * STR + ko;
                bh_[nt][0] = *(const u32*)&pBh[rb];
                bh_[nt][1] = *(const u32*)&pBh[rb + 8];
                bl_[nt][0] = *(const u32*)&pBl[rb];
                bl_[nt][1] = *(const u32*)&pBl[rb + 8];
            }
#pragma unroll
            for (int mt = 0; mt < 4; mt++) {
                int r0 = (wm*64 + mt*16 + g) * STR, r1 = r0 + 8*STR;
                u32 ah[4], al[4];
                ah[0] = *(const u32*)&pAh[r0 + ko];
                ah[1] = *(const u32*)&pAh[r1 + ko];
                ah[2] = *(const u32*)&pAh[r0 + ko + 8];
                ah[3] = *(const u32*)&pAh[r1 + ko + 8];
                al[0] = *(const u32*)&pAl[r0 + ko];
                al[1] = *(const u32*)&pAl[r1 + ko];
                al[2] = *(const u32*)&pAl[r0 + ko + 8];
                al[3] = *(const u32*)&pAl[r1 + ko + 8];
                // pass-major: independent mmas within each pass
#pragma unroll
                for (int nt = 0; nt < 4; nt++) mma16816(acc[mt][nt], ah, bh_[nt]);
#pragma unroll
                for (int nt = 0; nt < 4; nt++) mma16816(acc[mt][nt], ah, bl_[nt]);
#pragma unroll
                for (int nt = 0; nt < 4; nt++) mma16816(acc[mt][nt], al, bh_[nt]);
            }
        }
        __syncthreads();
    }
#undef ISSUE

    if (mode == 0) {
#pragma unroll
        for (int mt = 0; mt < 4; mt++) {
            int m = m0 + wm*64 + mt*16 + g;
#pragma unroll
            for (int nt = 0; nt < 4; nt++) {
                int c = n0 + wn*32 + nt*8 + 2*t;
                float b0 = bias[c], b1 = bias[c + 1];
                float2 v0 = make_float2(acc[mt][nt][0] + b0, acc[mt][nt][1] + b1);
                float2 v1 = make_float2(acc[mt][nt][2] + b0, acc[mt][nt][3] + b1);
                *(float2*)&C[(size_t)m * N + c] = v0;
                *(float2*)&C[(size_t)(m + 8) * N + c] = v1;
            }
        }
    } else {
        // QKV epilogue: bias + RoPE (+1/8 scale for q) + hi/lo split, scatter.
#pragma unroll
        for (int mt = 0; mt < 4; mt++) {
#pragma unroll
            for (int nt = 0; nt < 4; nt++) {
                int c = n0 + wn*32 + nt*8 + 2*t;
                float b0 = bias[c], b1 = bias[c + 1];
                int sec = c >> 10;                 // 0=q, 1=k, 2=v
                int h = (c & 1023) >> 6;
                int d2 = (c & 63) >> 1;
#pragma unroll
                for (int half = 0; half < 2; half++) {
                    int m = m0 + wm*64 + mt*16 + g + half*8;
                    int n = m & (SEQ - 1);
                    int b = m >> 11;
                    float v0 = acc[mt][nt][half*2]     + b0;
                    float v1 = acc[mt][nt][half*2 + 1] + b1;
                    float r0, r1;
                    ushortT *dh, *dl;
                    if (sec < 2) {
                        const float* p = &pe[((size_t)n * 32 + d2) * 4];
                        float p00 = p[0], p01 = p[1], p10 = p[2], p11 = p[3];
                        r0 = p00*v0 + p01*v1;
                        r1 = p10*v0 + p11*v1;
                        if (sec == 0) { r0 *= 0.125f; r1 *= 0.125f; dh = g_qh; dl = g_ql; }
                        else          { dh = g_kh; dl = g_kl; }
                    } else {
                        r0 = v0; r1 = v1; dh = g_vh; dl = g_vl;
                    }
                    size_t idx = (((size_t)(b * HEADS + h)) * SEQ + n) * 32 + d2;
                    u32 hh, ll;
                    splitpair(r0, r1, hh, ll);
                    ((u32*)dh)[idx] = hh;
                    ((u32*)dl)[idx] = ll;
                }
            }
        }
    }
}

// ---------------- k_mean -------------------------------------------------------
__global__ void kmean_kernel(float* __restrict__ out) {
    int idx = blockIdx.x * 256 + threadIdx.x;
    int d = idx & 63;
    int n = (idx >> 6) & 2047;
    int b = idx >> 17;
    float s = 0.0f;
#pragma unroll
    for (int h = 0; h < HEADS; h++) {
        size_t o = (((size_t)(b * HEADS + h)) * SEQ + n) * HDIM + d;
        s += u2f(g_kh[o]) + u2f(g_kl[o]);
    }
    out[idx] = s * (1.0f / 16.0f);
}

// ---------------- flash attention, bf16x3 mma.sync, pass-major mma order -------
#define VSTR 72
__global__ __launch_bounds__(256)
void flash_bf16x3() {
    __shared__ ushortT sKh[64*VSTR], sKl[64*VSTR], sVh[64*VSTR], sVl[64*VSTR];
    const int tid = threadIdx.x, lane = tid & 31, wid = tid >> 5;
    const int g = lane >> 2, t = lane & 3;
    const int bh = blockIdx.y;
    const int q0 = blockIdx.x * 128;
    const size_t base = (size_t)bh * SEQ * HDIM;

    u32 qfh[4][4], qfl[4][4];
    {
        int r0 = q0 + wid*16 + g;
        const ushortT* ph = g_qh + base + (size_t)r0 * HDIM;
        const ushortT* pl = g_ql + base + (size_t)r0 * HDIM;
#pragma unroll
        for (int c = 0; c < 4; c++) {
            int ko = c*16 + 2*t;
            qfh[c][0] = *(const u32*)(ph + ko);
            qfh[c][1] = *(const u32*)(ph + 8*HDIM + ko);
            qfh[c][2] = *(const u32*)(ph + ko + 8);
            qfh[c][3] = *(const u32*)(ph + 8*HDIM + ko + 8);
            qfl[c][0] = *(const u32*)(pl + ko);
            qfl[c][1] = *(const u32*)(pl + 8*HDIM + ko);
            qfl[c][2] = *(const u32*)(pl + ko + 8);
            qfl[c][3] = *(const u32*)(pl + 8*HDIM + ko + 8);
        }
    }

    float o[8][4];
#pragma unroll
    for (int a = 0; a < 8; a++)
#pragma unroll
        for (int b = 0; b < 4; b++) o[a][b] = 0.0f;
    float mi0 = -1e30f, mi1 = -1e30f, li0 = 0.0f, li1 = 0.0f;

    uint4 rkh[2], rkl[2], rvh[2], rvl[2];
#define LOADKV(N0) {                                                        \
    _Pragma("unroll")                                                       \
    for (int i = 0; i < 2; i++) {                                           \
        int sl = tid + i*256, row = sl >> 3, cg = sl & 7;                   \
        size_t off = base + (size_t)((N0) + row) * HDIM + cg*8;             \
        rkh[i] = *(const uint4*)(g_kh + off);                               \
        rkl[i] = *(const uint4*)(g_kl + off);                               \
        rvh[i] = *(const uint4*)(g_vh + off);                               \
        rvl[i] = *(const uint4*)(g_vl + off);                               \
    } }

    LOADKV(0);
    for (int it = 0; it < SEQ/64; it++) {
        __syncthreads();
#pragma unroll
        for (int i = 0; i < 2; i++) {
            int sl = tid + i*256, row = sl >> 3, cg = sl & 7;
            *(uint4*)&sKh[row*VSTR + cg*8] = rkh[i];
            *(uint4*)&sKl[row*VSTR + cg*8] = rkl[i];
            const ushortT* pv = (const ushortT*)&rvh[i];
            const ushortT* pw = (const ushortT*)&rvl[i];
#pragma unroll
            for (int e = 0; e < 8; e++) {
                sVh[(cg*8+e)*VSTR + row] = pv[e];
                sVl[(cg*8+e)*VSTR + row] = pw[e];
            }
        }
        __syncthreads();
        if (it + 1 < SEQ/64) LOADKV((it+1)*64);

        float sc[8][4];
#pragma unroll
        for (int a = 0; a < 8; a++)
#pragma unroll
            for (int b = 0; b < 4; b++) sc[a][b] = 0.0f;
        // S = Q K^T : pass-major (same-acc mmas 8 issues apart)
#pragma unroll
        for (int c = 0; c < 4; c++) {
            const int ko = c*16 + 2*t;
#pragma unroll
            for (int nt = 0; nt < 8; nt++) {
                int rb = (nt*8 + g)*VSTR + ko;
                u32 kb[2] = { *(const u32*)&sKh[rb], *(const u32*)&sKh[rb + 8] };
                mma16816(sc[nt], qfh[c], kb);
            }
#pragma unroll
            for (int nt = 0; nt < 8; nt++) {
                int rb = (nt*8 + g)*VSTR + ko;
                u32 kb[2] = { *(const u32*)&sKl[rb], *(const u32*)&sKl[rb + 8] };
                mma16816(sc[nt], qfh[c], kb);
            }
#pragma unroll
            for (int nt = 0; nt < 8; nt++) {
                int rb = (nt*8 + g)*VSTR + ko;
                u32 kb[2] = { *(const u32*)&sKh[rb], *(const u32*)&sKh[rb + 8] };
                mma16816(sc[nt], qfl[c], kb);
            }
        }

        float rm0 = -1e30f, rm1 = -1e30f;
#pragma unroll
        for (int nt = 0; nt < 8; nt++) {
            rm0 = fmaxf(rm0, fmaxf(sc[nt][0], sc[nt][1]));
            rm1 = fmaxf(rm1, fmaxf(sc[nt][2], sc[nt][3]));
        }
        rm0 = fmaxf(rm0, __shfl_xor_sync(0xffffffffu, rm0, 1));
        rm0 = fmaxf(rm0, __shfl_xor_sync(0xffffffffu, rm0, 2));
        rm1 = fmaxf(rm1, __shfl_xor_sync(0xffffffffu, rm1, 1));
        rm1 = fmaxf(rm1, __shfl_xor_sync(0xffffffffu, rm1, 2));
        float mn0 = fmaxf(mi0, rm0), mn1 = fmaxf(mi1, rm1);
        float a0 = __expf(mi0 - mn0), a1 = __expf(mi1 - mn1);
        float s0 = 0.0f, s1 = 0.0f;
#pragma unroll
        for (int nt = 0; nt < 8; nt++) {
            sc[nt][0] = __expf(sc[nt][0] - mn0); s0 += sc[nt][0];
            sc[nt][1] = __expf(sc[nt][1] - mn0); s0 += sc[nt][1];
            sc[nt][2] = __expf(sc[nt][2] - mn1); s1 += sc[nt][2];
            sc[nt][3] = __expf(sc[nt][3] - mn1); s1 += sc[nt][3];
        }
        s0 += __shfl_xor_sync(0xffffffffu, s0, 1);
        s0 += __shfl_xor_sync(0xffffffffu, s0, 2);
        s1 += __shfl_xor_sync(0xffffffffu, s1, 1);
        s1 += __shfl_xor_sync(0xffffffffu, s1, 2);
        li0 = li0 * a0 + s0; li1 = li1 * a1 + s1;
        mi0 = mn0; mi1 = mn1;
#pragma unroll
        for (int nt = 0; nt < 8; nt++) {
            o[nt][0] *= a0; o[nt][1] *= a0; o[nt][2] *= a1; o[nt][3] *= a1;
        }

        // O += P V : pass-major per j
#pragma unroll
        for (int j = 0; j < 4; j++) {
            u32 ph[4], pl[4];
            splitpair(sc[2*j][0],   sc[2*j][1],   ph[0], pl[0]);
            splitpair(sc[2*j][2],   sc[2*j][3],   ph[1], pl[1]);
            splitpair(sc[2*j+1][0], sc[2*j+1][1], ph[2], pl[2]);
            splitpair(sc[2*j+1][2], sc[2*j+1][3], ph[3], pl[3]);
            const int ko = j*16 + 2*t;
#pragma unroll
            for (int nt = 0; nt < 8; nt++) {
                int rb = (nt*8 + g)*VSTR + ko;
                u32 vb[2] = { *(const u32*)&sVh[rb], *(const u32*)&sVh[rb + 8] };
                mma16816(o[nt], ph, vb);
            }
#pragma unroll
            for (int nt = 0; nt < 8; nt++) {
                int rb = (nt*8 + g)*VSTR + ko;
                u32 vb[2] = { *(const u32*)&sVl[rb], *(const u32*)&sVl[rb + 8] };
                mma16816(o[nt], ph, vb);
            }
#pragma unroll
            for (int nt = 0; nt < 8; nt++) {
                int rb = (nt*8 + g)*VSTR + ko;
                u32 vb[2] = { *(const u32*)&sVh[rb], *(const u32*)&sVh[rb + 8] };
                mma16816(o[nt], pl, vb);
            }
        }
    }

    float i0 = 1.0f / li0, i1 = 1.0f / li1;
    int r0 = q0 + wid*16 + g;
#pragma unroll
    for (int nt = 0; nt < 8; nt++) {
        int col = nt*8 + 2*t;
        float2 v0 = make_float2(o[nt][0]*i0, o[nt][1]*i0);
        float2 v1 = make_float2(o[nt][2]*i1, o[nt][3]*i1);
        *(float2*)&g_o[base + (size_t)r0 * HDIM + col] = v0;
        *(float2*)&g_o[base + (size_t)(r0+8) * HDIM + col] = v1;
    }
#undef LOADKV
}

// ---------------- LayerNorm (gather heads, write bf16 hi/lo) -------------------
__global__ __launch_bounds__(256)
void ln_kernel(const float* __restrict__ gamma, const float* __restrict__ beta) {
    int bn = blockIdx.x;
    int b = bn >> 11;
    int n = bn & 2047;

    float vals[4];
    float s = 0.0f, ss = 0.0f;
#pragma unroll
    for (int ti = 0; ti < 4; ti++) {
        int c = threadIdx.x + ti * 256;
        int h = c >> 6, d = c & 63;
        float v = g_o[(((size_t)(b * HEADS + h)) * SEQ + n) * HDIM + d];
        vals[ti] = v; s += v; ss += v * v;
    }
#pragma unroll
    for (int m = 16; m; m >>= 1) {
        s  += __shfl_xor_sync(0xffffffffu, s, m);
        ss += __shfl_xor_sync(0xffffffffu, ss, m);
    }
    __shared__ float rs[8], rss[8];
    int w = threadIdx.x >> 5, lanei = threadIdx.x & 31;
    if (lanei == 0) { rs[w] = s; rss[w] = ss; }
    __syncthreads();
    float st = 0.0f, sst = 0.0f;
#pragma unroll
    for (int i = 0; i < 8; i++) { st += rs[i]; sst += rss[i]; }

    float mean = st * (1.0f / 1024.0f);
    float var  = sst * (1.0f / 1024.0f) - mean * mean;
    float r = rsqrtf(var + 1e-5f);
#pragma unroll
    for (int ti = 0; ti < 4; ti++) {
        int c = threadIdx.x + ti * 256;
        float f = (vals[ti] - mean) * r * gamma[c] + beta[c];
        unsigned short hh, ll; split1(f, hh, ll);
        g_lnh[(size_t)bn * DIM + c] = hh;
        g_lnl[(size_t)bn * DIM + c] = ll;
    }
}

// ---------------- launch --------------------------------------------------------
extern "C" void kernel_launch(void* const* d_in, const int* in_sizes, int n_in,
                              void* d_out, int out_size) {
    const float* x      = (const float*)d_in[0];
    const float* pe     = (const float*)d_in[1];
    const float* qkv_w  = (const float*)d_in[2];
    const float* q_bias = (const float*)d_in[3];
    const float* v_bias = (const float*)d_in[4];
    const float* gamma  = (const float*)d_in[5];
    const float* beta   = (const float*)d_in[6];
    const float* proj_w = (const float*)d_in[7];
    const float* proj_b = (const float*)d_in[8];
    float* out = (float*)d_out;

    void *p_bias3;
    void *p_xh, *p_xl, *p_wh, *p_wl, *p_pwh, *p_pwl, *p_lnh, *p_lnl;
    cudaGetSymbolAddress(&p_bias3, g_bias3);
    cudaGetSymbolAddress(&p_xh, g_xh);   cudaGetSymbolAddress(&p_xl, g_xl);
    cudaGetSymbolAddress(&p_wh, g_wh);   cudaGetSymbolAddress(&p_wl, g_wl);
    cudaGetSymbolAddress(&p_pwh, g_pwh); cudaGetSymbolAddress(&p_pwl, g_pwl);
    cudaGetSymbolAddress(&p_lnh, g_lnh); cudaGetSymbolAddress(&p_lnl, g_lnl);

    cudaFuncSetAttribute(gemm_bf16x3_v4,
                         cudaFuncAttributeMaxDynamicSharedMemorySize, GEMM_DSMEM);

    split_kernel<<<(MROWS*DIM + 255)/256, 256>>>(x, (ushortT*)p_xh, (ushortT*)p_xl, MROWS*DIM);
    split_kernel<<<(QKVN*DIM + 255)/256, 256>>>(qkv_w, (ushortT*)p_wh, (ushortT*)p_wl, QKVN*DIM);
    make_bias3_kernel<<<(QKVN + 255)/256, 256>>>(q_bias, v_bias);

    // QKV GEMM with fused bias + RoPE + hi/lo split epilogue
    gemm_bf16x3_v4<<<dim3(QKVN/BN, MROWS/BM), 256, GEMM_DSMEM>>>(
        (const ushortT*)p_xh, (const ushortT*)p_xl,
        (const ushortT*)p_wh, (const ushortT*)p_wl,
        (const float*)p_bias3, nullptr, MROWS, QKVN, DIM, 1, pe);

    split_kernel<<<(DIM*DIM + 255)/256, 256>>>(proj_w, (ushortT*)p_pwh, (ushortT*)p_pwl, DIM*DIM);
    kmean_kernel<<<(BATCH*SEQ*HDIM)/256, 256>>>(out + (size_t)MROWS * DIM);
    flash_bf16x3<<<dim3(SEQ/128, BH), 256>>>();
    ln_kernel<<<MROWS, 256>>>(gamma, beta);

    // projection GEMM -> d_out
    gemm_bf16x3_v4<<<dim3(DIM/BN, MROWS/BM), 256, GEMM_DSMEM>>>(
        (const ushortT*)p_lnh, (const ushortT*)p_lnl,
        (const ushortT*)p_pwh, (const ushortT*)p_pwl,
        proj_b, out, MROWS, DIM, DIM, 0, nullptr);
}

// round 10
// speedup vs baseline: 2.2174x; 1.0621x over previous
#include <cuda_runtime.h>
#include <cuda_bf16.h>
#include <math.h>

#define BATCH 2
#define SEQ   2048
#define DIM   1024
#define HEADS 16
#define HDIM  64
#define BH    (BATCH*HEADS)          // 32
#define MROWS (BATCH*SEQ)            // 4096
#define QKVN  (3*DIM)                // 3072

typedef unsigned short ushortT;
typedef unsigned int   u32;

// ---------------- scratch (device globals) -------------------------------------
__device__ float   g_o[BH * SEQ * HDIM];
__device__ float   g_bias3[QKVN];
__device__ ushortT g_xh[MROWS * DIM],  g_xl[MROWS * DIM];
__device__ ushortT g_wh[QKVN * DIM],   g_wl[QKVN * DIM];
__device__ ushortT g_pwh[DIM * DIM],   g_pwl[DIM * DIM];
__device__ ushortT g_qh[BH*SEQ*HDIM], g_ql[BH*SEQ*HDIM];
__device__ ushortT g_kh[BH*SEQ*HDIM], g_kl[BH*SEQ*HDIM];
__device__ ushortT g_vh[BH*SEQ*HDIM], g_vl[BH*SEQ*HDIM];
__device__ ushortT g_lnh[MROWS * DIM], g_lnl[MROWS * DIM];

// ---------------- helpers ------------------------------------------------------
__device__ __forceinline__ unsigned short b2u(__nv_bfloat16 x) {
    return *reinterpret_cast<unsigned short*>(&x);
}
__device__ __forceinline__ float u2f(unsigned short u) {
    __nv_bfloat16_raw r; r.x = u;
    __nv_bfloat16 b = r;
    return __bfloat162float(b);
}
__device__ __forceinline__ void split1(float x, unsigned short& h, unsigned short& l) {
    __nv_bfloat16 hb = __float2bfloat16_rn(x);
    float res = x - __bfloat162float(hb);
    __nv_bfloat16 lb = __float2bfloat16_rn(res);
    h = b2u(hb); l = b2u(lb);
}
__device__ __forceinline__ void splitpair(float x0, float x1, u32& h, u32& l) {
    unsigned short h0, l0, h1, l1;
    split1(x0, h0, l0); split1(x1, h1, l1);
    h = (u32)h0 | ((u32)h1 << 16);
    l = (u32)l0 | ((u32)l1 << 16);
}
__device__ __forceinline__ void mma16816(float* c, const u32* a, const u32* b) {
    asm volatile(
        "mma.sync.aligned.m16n8k16.row.col.f32.bf16.bf16.f32 "
        "{%0,%1,%2,%3}, {%4,%5,%6,%7}, {%8,%9}, {%0,%1,%2,%3};\n"
        : "+f"(c[0]), "+f"(c[1]), "+f"(c[2]), "+f"(c[3])
        : "r"(a[0]), "r"(a[1]), "r"(a[2]), "r"(a[3]), "r"(b[0]), "r"(b[1]));
}
__device__ __forceinline__ u32 smem_u32(const void* p) {
    return (u32)__cvta_generic_to_shared(p);
}
__device__ __forceinline__ void ldsm_x4(u32& r0, u32& r1, u32& r2, u32& r3, u32 addr) {
    asm volatile("ldmatrix.sync.aligned.m8n8.x4.shared.b16 {%0,%1,%2,%3}, [%4];"
                 : "=r"(r0), "=r"(r1), "=r"(r2), "=r"(r3) : "r"(addr));
}
__device__ __forceinline__ void cpasync16(u32 saddr, const void* g) {
    asm volatile("cp.async.cg.shared.global [%0], [%1], 16;" :: "r"(saddr), "l"(g) : "memory");
}

// ---------------- small kernels -------------------------------------------------
__global__ void split_kernel(const float* __restrict__ src, ushortT* __restrict__ h,
                             ushortT* __restrict__ l, int n) {
    int i = blockIdx.x * 256 + threadIdx.x;
    if (i < n) { unsigned short hh, ll; split1(src[i], hh, ll); h[i] = hh; l[i] = ll; }
}

__global__ void make_bias3_kernel(const float* __restrict__ qb,
                                  const float* __restrict__ vb) {
    int i = blockIdx.x * 256 + threadIdx.x;
    if (i >= QKVN) return;
    float v = 0.0f;
    if (i < DIM) v = qb[i];
    else if (i >= 2*DIM) v = vb[i - 2*DIM];
    g_bias3[i] = v;
}

// ---------------- GEMM bf16x3, 128x128 CTA, 64x32 warp tile, ldmatrix ----------
#define BM 128
#define BN 128
#define BKS 32
#define STR 40
#define ARR_U (BM * STR)                 // 5120 ushorts per sub-array
#define STAGE_U (4 * ARR_U)              // 20480 ushorts per stage
#define GEMM_DSMEM (2 * STAGE_U * 2)     // 81920 bytes

__global__ __launch_bounds__(256, 2)
void gemm_bf16x3_v5(const ushortT* __restrict__ Ah, const ushortT* __restrict__ Al,
                    const ushortT* __restrict__ Bh, const ushortT* __restrict__ Bl,
                    const float* __restrict__ bias, float* __restrict__ C,
                    int M, int N, int K, int mode, const float* __restrict__ pe) {
    extern __shared__ ushortT S[];
    const int tid = threadIdx.x, lane = tid & 31, wid = tid >> 5;
    const int wm = wid >> 2, wn = wid & 3;       // 2 x 4 warp grid
    const int g = lane >> 2, t = lane & 3;
    const int m0 = blockIdx.y * BM, n0 = blockIdx.x * BN;

    // ldmatrix lane-address constants
    const int a_row = lane & 15;                 // A: m-row within 16
    const int a_ko  = (lane >> 4) * 8;           // A: k offset select
    const int b_row = ((lane >> 4) << 3) | (lane & 7);   // B: n-row within pair
    const int b_ko  = ((lane >> 3) & 1) * 8;             // B: k offset select

    float acc[4][4][4];                          // [mt][nt][4]
#pragma unroll
    for (int a = 0; a < 4; a++)
#pragma unroll
        for (int b = 0; b < 4; b++)
#pragma unroll
            for (int c = 0; c < 4; c++) acc[a][b][c] = 0.0f;

#define ISSUE(SG) {                                                           \
    ushortT* st = S + ((SG) & 1) * STAGE_U;                                   \
    const int k0 = (SG) * BKS;                                                \
    _Pragma("unroll")                                                         \
    for (int i = 0; i < 2; i++) {                                             \
        int sl = tid + i*256, row = sl >> 2, cg = sl & 3;                     \
        size_t ga = (size_t)(m0 + row) * K + k0 + cg*8;                       \
        size_t gb = (size_t)(n0 + row) * K + k0 + cg*8;                       \
        u32 so = (u32)(row*STR + cg*8);                                       \
        cpasync16(smem_u32(st) + so*2, Ah + ga);                              \
        cpasync16(smem_u32(st + ARR_U) + so*2, Al + ga);                      \
        cpasync16(smem_u32(st + 2*ARR_U) + so*2, Bh + gb);                    \
        cpasync16(smem_u32(st + 3*ARR_U) + so*2, Bl + gb);                    \
    }                                                                         \
    asm volatile("cp.async.commit_group;" ::: "memory");                      \
    }

    const int NS = K / BKS;
    ISSUE(0);
    for (int s = 0; s < NS; s++) {
        if (s + 1 < NS) {
            ISSUE(s + 1);
            asm volatile("cp.async.wait_group 1;" ::: "memory");
        } else {
            asm volatile("cp.async.wait_group 0;" ::: "memory");
        }
        __syncthreads();

        const ushortT* st = S + (s & 1) * STAGE_U;
        const ushortT* pAh = st;
        const ushortT* pAl = st + ARR_U;
        const ushortT* pBh = st + 2*ARR_U;
        const ushortT* pBl = st + 3*ARR_U;
#pragma unroll
        for (int kc = 0; kc < 2; kc++) {
            u32 bh_[4][2], bl_[4][2];
#pragma unroll
            for (int pr = 0; pr < 2; pr++) {
                int off = (wn*32 + pr*16 + b_row) * STR + kc*16 + b_ko;
                ldsm_x4(bh_[2*pr][0], bh_[2*pr][1], bh_[2*pr+1][0], bh_[2*pr+1][1],
                        smem_u32(pBh + off));
                ldsm_x4(bl_[2*pr][0], bl_[2*pr][1], bl_[2*pr+1][0], bl_[2*pr+1][1],
                        smem_u32(pBl + off));
            }
#pragma unroll
            for (int mt = 0; mt < 4; mt++) {
                int aoff = (wm*64 + mt*16 + a_row) * STR + kc*16 + a_ko;
                u32 ah[4], al[4];
                ldsm_x4(ah[0], ah[1], ah[2], ah[3], smem_u32(pAh + aoff));
                ldsm_x4(al[0], al[1], al[2], al[3], smem_u32(pAl + aoff));
#pragma unroll
                for (int nt = 0; nt < 4; nt++) mma16816(acc[mt][nt], ah, bh_[nt]);
#pragma unroll
                for (int nt = 0; nt < 4; nt++) mma16816(acc[mt][nt], ah, bl_[nt]);
#pragma unroll
                for (int nt = 0; nt < 4; nt++) mma16816(acc[mt][nt], al, bh_[nt]);
            }
        }
        __syncthreads();
    }
#undef ISSUE

    if (mode == 0) {
#pragma unroll
        for (int mt = 0; mt < 4; mt++) {
            int m = m0 + wm*64 + mt*16 + g;
#pragma unroll
            for (int nt = 0; nt < 4; nt++) {
                int c = n0 + wn*32 + nt*8 + 2*t;
                float b0 = bias[c], b1 = bias[c + 1];
                float2 v0 = make_float2(acc[mt][nt][0] + b0, acc[mt][nt][1] + b1);
                float2 v1 = make_float2(acc[mt][nt][2] + b0, acc[mt][nt][3] + b1);
                *(float2*)&C[(size_t)m * N + c] = v0;
                *(float2*)&C[(size_t)(m + 8) * N + c] = v1;
            }
        }
    } else {
        // QKV epilogue: bias + RoPE (+1/8 scale for q) + hi/lo split, scatter.
#pragma unroll
        for (int mt = 0; mt < 4; mt++) {
#pragma unroll
            for (int nt = 0; nt < 4; nt++) {
                int c = n0 + wn*32 + nt*8 + 2*t;
                float b0 = bias[c], b1 = bias[c + 1];
                int sec = c >> 10;                 // 0=q, 1=k, 2=v
                int h = (c & 1023) >> 6;
                int d2 = (c & 63) >> 1;
#pragma unroll
                for (int half = 0; half < 2; half++) {
                    int m = m0 + wm*64 + mt*16 + g + half*8;
                    int n = m & (SEQ - 1);
                    int b = m >> 11;
                    float v0 = acc[mt][nt][half*2]     + b0;
                    float v1 = acc[mt][nt][half*2 + 1] + b1;
                    float r0, r1;
                    ushortT *dh, *dl;
                    if (sec < 2) {
                        const float* p = &pe[((size_t)n * 32 + d2) * 4];
                        float p00 = p[0], p01 = p[1], p10 = p[2], p11 = p[3];
                        r0 = p00*v0 + p01*v1;
                        r1 = p10*v0 + p11*v1;
                        if (sec == 0) { r0 *= 0.125f; r1 *= 0.125f; dh = g_qh; dl = g_ql; }
                        else          { dh = g_kh; dl = g_kl; }
                    } else {
                        r0 = v0; r1 = v1; dh = g_vh; dl = g_vl;
                    }
                    size_t idx = (((size_t)(b * HEADS + h)) * SEQ + n) * 32 + d2;
                    u32 hh, ll;
                    splitpair(r0, r1, hh, ll);
                    ((u32*)dh)[idx] = hh;
                    ((u32*)dl)[idx] = ll;
                }
            }
        }
    }
}

// ---------------- k_mean -------------------------------------------------------
__global__ void kmean_kernel(float* __restrict__ out) {
    int idx = blockIdx.x * 256 + threadIdx.x;
    int d = idx & 63;
    int n = (idx >> 6) & 2047;
    int b = idx >> 17;
    float s = 0.0f;
#pragma unroll
    for (int h = 0; h < HEADS; h++) {
        size_t o = (((size_t)(b * HEADS + h)) * SEQ + n) * HDIM + d;
        s += u2f(g_kh[o]) + u2f(g_kl[o]);
    }
    out[idx] = s * (1.0f / 16.0f);
}

// ---------------- flash attention, bf16x3 mma.sync + ldmatrix ------------------
#define VSTR 72
__global__ __launch_bounds__(256)
void flash_bf16x3() {
    __shared__ ushortT sKh[64*VSTR], sKl[64*VSTR], sVh[64*VSTR], sVl[64*VSTR];
    const int tid = threadIdx.x, lane = tid & 31, wid = tid >> 5;
    const int g = lane >> 2, t = lane & 3;
    const int bh = blockIdx.y;
    const int q0 = blockIdx.x * 128;
    const size_t base = (size_t)bh * SEQ * HDIM;

    const int b_row = ((lane >> 4) << 3) | (lane & 7);
    const int b_ko  = ((lane >> 3) & 1) * 8;

    u32 qfh[4][4], qfl[4][4];
    {
        int r0 = q0 + wid*16 + g;
        const ushortT* ph = g_qh + base + (size_t)r0 * HDIM;
        const ushortT* pl = g_ql + base + (size_t)r0 * HDIM;
#pragma unroll
        for (int c = 0; c < 4; c++) {
            int ko = c*16 + 2*t;
            qfh[c][0] = *(const u32*)(ph + ko);
            qfh[c][1] = *(const u32*)(ph + 8*HDIM + ko);
            qfh[c][2] = *(const u32*)(ph + ko + 8);
            qfh[c][3] = *(const u32*)(ph + 8*HDIM + ko + 8);
            qfl[c][0] = *(const u32*)(pl + ko);
            qfl[c][1] = *(const u32*)(pl + 8*HDIM + ko);
            qfl[c][2] = *(const u32*)(pl + ko + 8);
            qfl[c][3] = *(const u32*)(pl + 8*HDIM + ko + 8);
        }
    }

    float o[8][4];
#pragma unroll
    for (int a = 0; a < 8; a++)
#pragma unroll
        for (int b = 0; b < 4; b++) o[a][b] = 0.0f;
    float mi0 = -1e30f, mi1 = -1e30f, li0 = 0.0f, li1 = 0.0f;

    uint4 rkh[2], rkl[2], rvh[2], rvl[2];
#define LOADKV(N0) {                                                        \
    _Pragma("unroll")                                                       \
    for (int i = 0; i < 2; i++) {                                           \
        int sl = tid + i*256, row = sl >> 3, cg = sl & 7;                   \
        size_t off = base + (size_t)((N0) + row) * HDIM + cg*8;             \
        rkh[i] = *(const uint4*)(g_kh + off);                               \
        rkl[i] = *(const uint4*)(g_kl + off);                               \
        rvh[i] = *(const uint4*)(g_vh + off);                               \
        rvl[i] = *(const uint4*)(g_vl + off);                               \
    } }

    LOADKV(0);
    for (int it = 0; it < SEQ/64; it++) {
        __syncthreads();
#pragma unroll
        for (int i = 0; i < 2; i++) {
            int sl = tid + i*256, row = sl >> 3, cg = sl & 7;
            *(uint4*)&sKh[row*VSTR + cg*8] = rkh[i];
            *(uint4*)&sKl[row*VSTR + cg*8] = rkl[i];
            const ushortT* pv = (const ushortT*)&rvh[i];
            const ushortT* pw = (const ushortT*)&rvl[i];
#pragma unroll
            for (int e = 0; e < 8; e++) {
                sVh[(cg*8+e)*VSTR + row] = pv[e];
                sVl[(cg*8+e)*VSTR + row] = pw[e];
            }
        }
        __syncthreads();
        if (it + 1 < SEQ/64) LOADKV((it+1)*64);

        float sc[8][4];
#pragma unroll
        for (int a = 0; a < 8; a++)
#pragma unroll
            for (int b = 0; b < 4; b++) sc[a][b] = 0.0f;
        // S = Q K^T : ldmatrix fragments, pass-major
#pragma unroll
        for (int c = 0; c < 4; c++) {
            const int kbase = c*16 + b_ko;
            u32 kb[8][2];
#pragma unroll
            for (int pr = 0; pr < 4; pr++)
                ldsm_x4(kb[2*pr][0], kb[2*pr][1], kb[2*pr+1][0], kb[2*pr+1][1],
                        smem_u32(&sKh[(pr*16 + b_row)*VSTR + kbase]));
#pragma unroll
            for (int nt = 0; nt < 8; nt++) mma16816(sc[nt], qfh[c], kb[nt]);
#pragma unroll
            for (int pr = 0; pr < 4; pr++)
                ldsm_x4(kb[2*pr][0], kb[2*pr][1], kb[2*pr+1][0], kb[2*pr+1][1],
                        smem_u32(&sKl[(pr*16 + b_row)*VSTR + kbase]));
#pragma unroll
            for (int nt = 0; nt < 8; nt++) mma16816(sc[nt], qfh[c], kb[nt]);
#pragma unroll
            for (int pr = 0; pr < 4; pr++)
                ldsm_x4(kb[2*pr][0], kb[2*pr][1], kb[2*pr+1][0], kb[2*pr+1][1],
                        smem_u32(&sKh[(pr*16 + b_row)*VSTR + kbase]));
#pragma unroll
            for (int nt = 0; nt < 8; nt++) mma16816(sc[nt], qfl[c], kb[nt]);
        }

        float rm0 = -1e30f, rm1 = -1e30f;
#pragma unroll
        for (int nt = 0; nt < 8; nt++) {
            rm0 = fmaxf(rm0, fmaxf(sc[nt][0], sc[nt][1]));
            rm1 = fmaxf(rm1, fmaxf(sc[nt][2], sc[nt][3]));
        }
        rm0 = fmaxf(rm0, __shfl_xor_sync(0xffffffffu, rm0, 1));
        rm0 = fmaxf(rm0, __shfl_xor_sync(0xffffffffu, rm0, 2));
        rm1 = fmaxf(rm1, __shfl_xor_sync(0xffffffffu, rm1, 1));
        rm1 = fmaxf(rm1, __shfl_xor_sync(0xffffffffu, rm1, 2));
        float mn0 = fmaxf(mi0, rm0), mn1 = fmaxf(mi1, rm1);
        float a0 = __expf(mi0 - mn0), a1 = __expf(mi1 - mn1);
        float s0 = 0.0f, s1 = 0.0f;
#pragma unroll
        for (int nt = 0; nt < 8; nt++) {
            sc[nt][0] = __expf(sc[nt][0] - mn0); s0 += sc[nt][0];
            sc[nt][1] = __expf(sc[nt][1] - mn0); s0 += sc[nt][1];
            sc[nt][2] = __expf(sc[nt][2] - mn1); s1 += sc[nt][2];
            sc[nt][3] = __expf(sc[nt][3] - mn1); s1 += sc[nt][3];
        }
        s0 += __shfl_xor_sync(0xffffffffu, s0, 1);
        s0 += __shfl_xor_sync(0xffffffffu, s0, 2);
        s1 += __shfl_xor_sync(0xffffffffu, s1, 1);
        s1 += __shfl_xor_sync(0xffffffffu, s1, 2);
        li0 = li0 * a0 + s0; li1 = li1 * a1 + s1;
        mi0 = mn0; mi1 = mn1;
#pragma unroll
        for (int nt = 0; nt < 8; nt++) {
            o[nt][0] *= a0; o[nt][1] *= a0; o[nt][2] *= a1; o[nt][3] *= a1;
        }

        // O += P V : ldmatrix fragments, pass-major per j
#pragma unroll
        for (int j = 0; j < 4; j++) {
            u32 ph[4], pl[4];
            splitpair(sc[2*j][0],   sc[2*j][1],   ph[0], pl[0]);
            splitpair(sc[2*j][2],   sc[2*j][3],   ph[1], pl[1]);
            splitpair(sc[2*j+1][0], sc[2*j+1][1], ph[2], pl[2]);
            splitpair(sc[2*j+1][2], sc[2*j+1][3], ph[3], pl[3]);
            const int kbase = j*16 + b_ko;
            u32 vb[8][2];
#pragma unroll
            for (int pr = 0; pr < 4; pr++)
                ldsm_x4(vb[2*pr][0], vb[2*pr][1], vb[2*pr+1][0], vb[2*pr+1][1],
                        smem_u32(&sVh[(pr*16 + b_row)*VSTR + kbase]));
#pragma unroll
            for (int nt = 0; nt < 8; nt++) mma16816(o[nt], ph, vb[nt]);
#pragma unroll
            for (int pr = 0; pr < 4; pr++)
                ldsm_x4(vb[2*pr][0], vb[2*pr][1], vb[2*pr+1][0], vb[2*pr+1][1],
                        smem_u32(&sVl[(pr*16 + b_row)*VSTR + kbase]));
#pragma unroll
            for (int nt = 0; nt < 8; nt++) mma16816(o[nt], ph, vb[nt]);
#pragma unroll
            for (int pr = 0; pr < 4; pr++)
                ldsm_x4(vb[2*pr][0], vb[2*pr][1], vb[2*pr+1][0], vb[2*pr+1][1],
                        smem_u32(&sVh[(pr*16 + b_row)*VSTR + kbase]));
#pragma unroll
            for (int nt = 0; nt < 8; nt++) mma16816(o[nt], pl, vb[nt]);
        }
    }

    float i0 = 1.0f / li0, i1 = 1.0f / li1;
    int r0 = q0 + wid*16 + g;
#pragma unroll
    for (int nt = 0; nt < 8; nt++) {
        int col = nt*8 + 2*t;
        float2 v0 = make_float2(o[nt][0]*i0, o[nt][1]*i0);
        float2 v1 = make_float2(o[nt][2]*i1, o[nt][3]*i1);
        *(float2*)&g_o[base + (size_t)r0 * HDIM + col] = v0;
        *(float2*)&g_o[base + (size_t)(r0+8) * HDIM + col] = v1;
    }
#undef LOADKV
}

// ---------------- LayerNorm (gather heads, write bf16 hi/lo) -------------------
__global__ __launch_bounds__(256)
void ln_kernel(const float* __restrict__ gamma, const float* __restrict__ beta) {
    int bn = blockIdx.x;
    int b = bn >> 11;
    int n = bn & 2047;

    float vals[4];
    float s = 0.0f, ss = 0.0f;
#pragma unroll
    for (int ti = 0; ti < 4; ti++) {
        int c = threadIdx.x + ti * 256;
        int h = c >> 6, d = c & 63;
        float v = g_o[(((size_t)(b * HEADS + h)) * SEQ + n) * HDIM + d];
        vals[ti] = v; s += v; ss += v * v;
    }
#pragma unroll
    for (int m = 16; m; m >>= 1) {
        s  += __shfl_xor_sync(0xffffffffu, s, m);
        ss += __shfl_xor_sync(0xffffffffu, ss, m);
    }
    __shared__ float rs[8], rss[8];
    int w = threadIdx.x >> 5, lanei = threadIdx.x & 31;
    if (lanei == 0) { rs[w] = s; rss[w] = ss; }
    __syncthreads();
    float st = 0.0f, sst = 0.0f;
#pragma unroll
    for (int i = 0; i < 8; i++) { st += rs[i]; sst += rss[i]; }

    float mean = st * (1.0f / 1024.0f);
    float var  = sst * (1.0f / 1024.0f) - mean * mean;
    float r = rsqrtf(var + 1e-5f);
#pragma unroll
    for (int ti = 0; ti < 4; ti++) {
        int c = threadIdx.x + ti * 256;
        float f = (vals[ti] - mean) * r * gamma[c] + beta[c];
        unsigned short hh, ll; split1(f, hh, ll);
        g_lnh[(size_t)bn * DIM + c] = hh;
        g_lnl[(size_t)bn * DIM + c] = ll;
    }
}

// ---------------- launch --------------------------------------------------------
extern "C" void kernel_launch(void* const* d_in, const int* in_sizes, int n_in,
                              void* d_out, int out_size) {
    const float* x      = (const float*)d_in[0];
    const float* pe     = (const float*)d_in[1];
    const float* qkv_w  = (const float*)d_in[2];
    const float* q_bias = (const float*)d_in[3];
    const float* v_bias = (const float*)d_in[4];
    const float* gamma  = (const float*)d_in[5];
    const float* beta   = (const float*)d_in[6];
    const float* proj_w = (const float*)d_in[7];
    const float* proj_b = (const float*)d_in[8];
    float* out = (float*)d_out;

    void *p_bias3;
    void *p_xh, *p_xl, *p_wh, *p_wl, *p_pwh, *p_pwl, *p_lnh, *p_lnl;
    cudaGetSymbolAddress(&p_bias3, g_bias3);
    cudaGetSymbolAddress(&p_xh, g_xh);   cudaGetSymbolAddress(&p_xl, g_xl);
    cudaGetSymbolAddress(&p_wh, g_wh);   cudaGetSymbolAddress(&p_wl, g_wl);
    cudaGetSymbolAddress(&p_pwh, g_pwh); cudaGetSymbolAddress(&p_pwl, g_pwl);
    cudaGetSymbolAddress(&p_lnh, g_lnh); cudaGetSymbolAddress(&p_lnl, g_lnl);

    cudaFuncSetAttribute(gemm_bf16x3_v5,
                         cudaFuncAttributeMaxDynamicSharedMemorySize, GEMM_DSMEM);

    split_kernel<<<(MROWS*DIM + 255)/256, 256>>>(x, (ushortT*)p_xh, (ushortT*)p_xl, MROWS*DIM);
    split_kernel<<<(QKVN*DIM + 255)/256, 256>>>(qkv_w, (ushortT*)p_wh, (ushortT*)p_wl, QKVN*DIM);
    make_bias3_kernel<<<(QKVN + 255)/256, 256>>>(q_bias, v_bias);

    // QKV GEMM with fused bias + RoPE + hi/lo split epilogue
    gemm_bf16x3_v5<<<dim3(QKVN/BN, MROWS/BM), 256, GEMM_DSMEM>>>(
        (const ushortT*)p_xh, (const ushortT*)p_xl,
        (const ushortT*)p_wh, (const ushortT*)p_wl,
        (const float*)p_bias3, nullptr, MROWS, QKVN, DIM, 1, pe);

    split_kernel<<<(DIM*DIM + 255)/256, 256>>>(proj_w, (ushortT*)p_pwh, (ushortT*)p_pwl, DIM*DIM);
    kmean_kernel<<<(BATCH*SEQ*HDIM)/256, 256>>>(out + (size_t)MROWS * DIM);
    flash_bf16x3<<<dim3(SEQ/128, BH), 256>>>();
    ln_kernel<<<MROWS, 256>>>(gamma, beta);

    // projection GEMM -> d_out
    gemm_bf16x3_v5<<<dim3(DIM/BN, MROWS/BM), 256, GEMM_DSMEM>>>(
        (const ushortT*)p_lnh, (const ushortT*)p_lnl,
        (const ushortT*)p_pwh, (const ushortT*)p_pwl,
        proj_b, out, MROWS, DIM, DIM, 0, nullptr);
}

// round 12
// speedup vs baseline: 2.6559x; 1.1977x over previous
#include <cuda_runtime.h>
#include <cuda_bf16.h>
#include <math.h>

#define BATCH 2
#define SEQ   2048
#define DIM   1024
#define HEADS 16
#define HDIM  64
#define BH    (BATCH*HEADS)          // 32
#define MROWS (BATCH*SEQ)            // 4096
#define QKVN  (3*DIM)                // 3072

typedef unsigned short ushortT;
typedef unsigned int   u32;

// ---------------- scratch (device globals) -------------------------------------
__device__ float   g_o[BH * SEQ * HDIM];
__device__ float   g_bias3[QKVN];
__device__ ushortT g_xh[MROWS * DIM],  g_xl[MROWS * DIM];
__device__ ushortT g_wh[QKVN * DIM],   g_wl[QKVN * DIM];
__device__ ushortT g_pwh[DIM * DIM],   g_pwl[DIM * DIM];
__device__ ushortT g_qh[BH*SEQ*HDIM], g_ql[BH*SEQ*HDIM];
__device__ ushortT g_kh[BH*SEQ*HDIM], g_kl[BH*SEQ*HDIM];
__device__ ushortT g_vh[BH*SEQ*HDIM], g_vl[BH*SEQ*HDIM];
__device__ ushortT g_lnh[MROWS * DIM], g_lnl[MROWS * DIM];

// ---------------- helpers ------------------------------------------------------
__device__ __forceinline__ unsigned short b2u(__nv_bfloat16 x) {
    return *reinterpret_cast<unsigned short*>(&x);
}
__device__ __forceinline__ float u2f(unsigned short u) {
    __nv_bfloat16_raw r; r.x = u;
    __nv_bfloat16 b = r;
    return __bfloat162float(b);
}
__device__ __forceinline__ void split1(float x, unsigned short& h, unsigned short& l) {
    __nv_bfloat16 hb = __float2bfloat16_rn(x);
    float res = x - __bfloat162float(hb);
    __nv_bfloat16 lb = __float2bfloat16_rn(res);
    h = b2u(hb); l = b2u(lb);
}
__device__ __forceinline__ void splitpair(float x0, float x1, u32& h, u32& l) {
    unsigned short h0, l0, h1, l1;
    split1(x0, h0, l0); split1(x1, h1, l1);
    h = (u32)h0 | ((u32)h1 << 16);
    l = (u32)l0 | ((u32)l1 << 16);
}
__device__ __forceinline__ void mma16816(float* c, const u32* a, const u32* b) {
    asm volatile(
        "mma.sync.aligned.m16n8k16.row.col.f32.bf16.bf16.f32 "
        "{%0,%1,%2,%3}, {%4,%5,%6,%7}, {%8,%9}, {%0,%1,%2,%3};\n"
        : "+f"(c[0]), "+f"(c[1]), "+f"(c[2]), "+f"(c[3])
        : "r"(a[0]), "r"(a[1]), "r"(a[2]), "r"(a[3]), "r"(b[0]), "r"(b[1]));
}
__device__ __forceinline__ u32 smem_u32(const void* p) {
    return (u32)__cvta_generic_to_shared(p);
}
__device__ __forceinline__ void ldsm_x4(u32& r0, u32& r1, u32& r2, u32& r3, u32 addr) {
    asm volatile("ldmatrix.sync.aligned.m8n8.x4.shared.b16 {%0,%1,%2,%3}, [%4];"
                 : "=r"(r0), "=r"(r1), "=r"(r2), "=r"(r3) : "r"(addr));
}
__device__ __forceinline__ void ldsm_x4_trans(u32& r0, u32& r1, u32& r2, u32& r3, u32 addr) {
    asm volatile("ldmatrix.sync.aligned.m8n8.x4.trans.shared.b16 {%0,%1,%2,%3}, [%4];"
                 : "=r"(r0), "=r"(r1), "=r"(r2), "=r"(r3) : "r"(addr));
}
__device__ __forceinline__ void cpasync16(u32 saddr, const void* g) {
    asm volatile("cp.async.cg.shared.global [%0], [%1], 16;" :: "r"(saddr), "l"(g) : "memory");
}

// ---------------- fused prologue: all splits + merged bias ---------------------
#define XN (MROWS*DIM)           // 4194304
#define WN (QKVN*DIM)            // 3145728
#define PWN (DIM*DIM)            // 1048576
#define TOTSPLIT (XN + WN + PWN + QKVN)

__global__ void fused_split_kernel(const float* __restrict__ x,
                                   const float* __restrict__ qkv_w,
                                   const float* __restrict__ proj_w,
                                   const float* __restrict__ qb,
                                   const float* __restrict__ vb) {
    int i = blockIdx.x * 256 + threadIdx.x;
    if (i < XN) {
        unsigned short hh, ll; split1(x[i], hh, ll);
        g_xh[i] = hh; g_xl[i] = ll;
    } else if (i < XN + WN) {
        int j = i - XN;
        unsigned short hh, ll; split1(qkv_w[j], hh, ll);
        g_wh[j] = hh; g_wl[j] = ll;
    } else if (i < XN + WN + PWN) {
        int j = i - XN - WN;
        unsigned short hh, ll; split1(proj_w[j], hh, ll);
        g_pwh[j] = hh; g_pwl[j] = ll;
    } else if (i < TOTSPLIT) {
        int j = i - XN - WN - PWN;
        float v = 0.0f;
        if (j < DIM) v = qb[j];
        else if (j >= 2*DIM) v = vb[j - 2*DIM];
        g_bias3[j] = v;
    }
}

// ---------------- GEMM bf16x3, 128x128 CTA, 64x32 warp tile, ldmatrix ----------
#define BM 128
#define BN 128
#define BKS 32
#define STR 40
#define ARR_U (BM * STR)                 // 5120 ushorts per sub-array
#define STAGE_U (4 * ARR_U)              // 20480 ushorts per stage
#define GEMM_DSMEM (2 * STAGE_U * 2)     // 81920 bytes

__global__ __launch_bounds__(256, 2)
void gemm_bf16x3_v5(const ushortT* __restrict__ Ah, const ushortT* __restrict__ Al,
                    const ushortT* __restrict__ Bh, const ushortT* __restrict__ Bl,
                    const float* __restrict__ bias, float* __restrict__ C,
                    int M, int N, int K, int mode, const float* __restrict__ pe) {
    extern __shared__ ushortT S[];
    const int tid = threadIdx.x, lane = tid & 31, wid = tid >> 5;
    const int wm = wid >> 2, wn = wid & 3;       // 2 x 4 warp grid
    const int g = lane >> 2, t = lane & 3;
    const int m0 = blockIdx.y * BM, n0 = blockIdx.x * BN;

    // ldmatrix lane-address constants
    const int a_row = lane & 15;                 // A: m-row within 16
    const int a_ko  = (lane >> 4) * 8;           // A: k offset select
    const int b_row = ((lane >> 4) << 3) | (lane & 7);   // B: n-row within pair
    const int b_ko  = ((lane >> 3) & 1) * 8;             // B: k offset select

    float acc[4][4][4];                          // [mt][nt][4]
#pragma unroll
    for (int a = 0; a < 4; a++)
#pragma unroll
        for (int b = 0; b < 4; b++)
#pragma unroll
            for (int c = 0; c < 4; c++) acc[a][b][c] = 0.0f;

#define ISSUE(SG) {                                                           \
    ushortT* st = S + ((SG) & 1) * STAGE_U;                                   \
    const int k0 = (SG) * BKS;                                                \
    _Pragma("unroll")                                                         \
    for (int i = 0; i < 2; i++) {                                             \
        int sl = tid + i*256, row = sl >> 2, cg = sl & 3;                     \
        size_t ga = (size_t)(m0 + row) * K + k0 + cg*8;                       \
        size_t gb = (size_t)(n0 + row) * K + k0 + cg*8;                       \
        u32 so = (u32)(row*STR + cg*8);                                       \
        cpasync16(smem_u32(st) + so*2, Ah + ga);                              \
        cpasync16(smem_u32(st + ARR_U) + so*2, Al + ga);                      \
        cpasync16(smem_u32(st + 2*ARR_U) + so*2, Bh + gb);                    \
        cpasync16(smem_u32(st + 3*ARR_U) + so*2, Bl + gb);                    \
    }                                                                         \
    asm volatile("cp.async.commit_group;" ::: "memory");                      \
    }

    const int NS = K / BKS;
    ISSUE(0);
    for (int s = 0; s < NS; s++) {
        if (s + 1 < NS) {
            ISSUE(s + 1);
            asm volatile("cp.async.wait_group 1;" ::: "memory");
        } else {
            asm volatile("cp.async.wait_group 0;" ::: "memory");
        }
        __syncthreads();

        const ushortT* st = S + (s & 1) * STAGE_U;
        const ushortT* pAh = st;
        const ushortT* pAl = st + ARR_U;
        const ushortT* pBh = st + 2*ARR_U;
        const ushortT* pBl = st + 3*ARR_U;
#pragma unroll
        for (int kc = 0; kc < 2; kc++) {
            u32 bh_[4][2], bl_[4][2];
#pragma unroll
            for (int pr = 0; pr < 2; pr++) {
                int off = (wn*32 + pr*16 + b_row) * STR + kc*16 + b_ko;
                ldsm_x4(bh_[2*pr][0], bh_[2*pr][1], bh_[2*pr+1][0], bh_[2*pr+1][1],
                        smem_u32(pBh + off));
                ldsm_x4(bl_[2*pr][0], bl_[2*pr][1], bl_[2*pr+1][0], bl_[2*pr+1][1],
                        smem_u32(pBl + off));
            }
#pragma unroll
            for (int mt = 0; mt < 4; mt++) {
                int aoff = (wm*64 + mt*16 + a_row) * STR + kc*16 + a_ko;
                u32 ah[4], al[4];
                ldsm_x4(ah[0], ah[1], ah[2], ah[3], smem_u32(pAh + aoff));
                ldsm_x4(al[0], al[1], al[2], al[3], smem_u32(pAl + aoff));
#pragma unroll
                for (int nt = 0; nt < 4; nt++) mma16816(acc[mt][nt], ah, bh_[nt]);
#pragma unroll
                for (int nt = 0; nt < 4; nt++) mma16816(acc[mt][nt], ah, bl_[nt]);
#pragma unroll
                for (int nt = 0; nt < 4; nt++) mma16816(acc[mt][nt], al, bh_[nt]);
            }
        }
        __syncthreads();
    }
#undef ISSUE

    if (mode == 0) {
#pragma unroll
        for (int mt = 0; mt < 4; mt++) {
            int m = m0 + wm*64 + mt*16 + g;
#pragma unroll
            for (int nt = 0; nt < 4; nt++) {
                int c = n0 + wn*32 + nt*8 + 2*t;
                float b0 = bias[c], b1 = bias[c + 1];
                float2 v0 = make_float2(acc[mt][nt][0] + b0, acc[mt][nt][1] + b1);
                float2 v1 = make_float2(acc[mt][nt][2] + b0, acc[mt][nt][3] + b1);
                *(float2*)&C[(size_t)m * N + c] = v0;
                *(float2*)&C[(size_t)(m + 8) * N + c] = v1;
            }
        }
    } else {
        // QKV epilogue: bias + RoPE (+1/8 scale for q) + hi/lo split, scatter.
#pragma unroll
        for (int mt = 0; mt < 4; mt++) {
#pragma unroll
            for (int nt = 0; nt < 4; nt++) {
                int c = n0 + wn*32 + nt*8 + 2*t;
                float b0 = bias[c], b1 = bias[c + 1];
                int sec = c >> 10;                 // 0=q, 1=k, 2=v
                int h = (c & 1023) >> 6;
                int d2 = (c & 63) >> 1;
#pragma unroll
                for (int half = 0; half < 2; half++) {
                    int m = m0 + wm*64 + mt*16 + g + half*8;
                    int n = m & (SEQ - 1);
                    int b = m >> 11;
                    float v0 = acc[mt][nt][half*2]     + b0;
                    float v1 = acc[mt][nt][half*2 + 1] + b1;
                    float r0, r1;
                    ushortT *dh, *dl;
                    if (sec < 2) {
                        const float* p = &pe[((size_t)n * 32 + d2) * 4];
                        float p00 = p[0], p01 = p[1], p10 = p[2], p11 = p[3];
                        r0 = p00*v0 + p01*v1;
                        r1 = p10*v0 + p11*v1;
                        if (sec == 0) { r0 *= 0.125f; r1 *= 0.125f; dh = g_qh; dl = g_ql; }
                        else          { dh = g_kh; dl = g_kl; }
                    } else {
                        r0 = v0; r1 = v1; dh = g_vh; dl = g_vl;
                    }
                    size_t idx = (((size_t)(b * HEADS + h)) * SEQ + n) * 32 + d2;
                    u32 hh, ll;
                    splitpair(r0, r1, hh, ll);
                    ((u32*)dh)[idx] = hh;
                    ((u32*)dl)[idx] = ll;
                }
            }
        }
    }
}

// ---------------- k_mean -------------------------------------------------------
__global__ void kmean_kernel(float* __restrict__ out) {
    int idx = blockIdx.x * 256 + threadIdx.x;
    int d = idx & 63;
    int n = (idx >> 6) & 2047;
    int b = idx >> 17;
    float s = 0.0f;
#pragma unroll
    for (int h = 0; h < HEADS; h++) {
        size_t o = (((size_t)(b * HEADS + h)) * SEQ + n) * HDIM + d;
        s += u2f(g_kh[o]) + u2f(g_kl[o]);
    }
    out[idx] = s * (1.0f / 16.0f);
}

// ---------------- flash attention, bf16x3 mma.sync + ldmatrix(.trans) ----------
#define VSTR 72
__global__ __launch_bounds__(256)
void flash_bf16x3() {
    __shared__ ushortT sKh[64*VSTR], sKl[64*VSTR], sVh[64*VSTR], sVl[64*VSTR];
    const int tid = threadIdx.x, lane = tid & 31, wid = tid >> 5;
    const int g = lane >> 2, t = lane & 3;
    const int bh = blockIdx.y;
    const int q0 = blockIdx.x * 128;
    const size_t base = (size_t)bh * SEQ * HDIM;

    const int b_row = ((lane >> 4) << 3) | (lane & 7);
    const int b_ko  = ((lane >> 3) & 1) * 8;
    // trans-ldmatrix lane map for V ([k=seq][n=d] storage)
    const int v_row = ((lane >> 3) & 1) * 8 + (lane & 7);   // k row within 16
    const int v_col = (lane >> 4) * 8;                      // d col within 16

    u32 qfh[4][4], qfl[4][4];
    {
        int r0 = q0 + wid*16 + g;
        const ushortT* ph = g_qh + base + (size_t)r0 * HDIM;
        const ushortT* pl = g_ql + base + (size_t)r0 * HDIM;
#pragma unroll
        for (int c = 0; c < 4; c++) {
            int ko = c*16 + 2*t;
            qfh[c][0] = *(const u32*)(ph + ko);
            qfh[c][1] = *(const u32*)(ph + 8*HDIM + ko);
            qfh[c][2] = *(const u32*)(ph + ko + 8);
            qfh[c][3] = *(const u32*)(ph + 8*HDIM + ko + 8);
            qfl[c][0] = *(const u32*)(pl + ko);
            qfl[c][1] = *(const u32*)(pl + 8*HDIM + ko);
            qfl[c][2] = *(const u32*)(pl + ko + 8);
            qfl[c][3] = *(const u32*)(pl + 8*HDIM + ko + 8);
        }
    }

    float o[8][4];
#pragma unroll
    for (int a = 0; a < 8; a++)
#pragma unroll
        for (int b = 0; b < 4; b++) o[a][b] = 0.0f;
    float mi0 = -1e30f, mi1 = -1e30f, li0 = 0.0f, li1 = 0.0f;

    uint4 rkh[2], rkl[2], rvh[2], rvl[2];
#define LOADKV(N0) {                                                        \
    _Pragma("unroll")                                                       \
    for (int i = 0; i < 2; i++) {                                           \
        int sl = tid + i*256, row = sl >> 3, cg = sl & 7;                   \
        size_t off = base + (size_t)((N0) + row) * HDIM + cg*8;             \
        rkh[i] = *(const uint4*)(g_kh + off);                               \
        rkl[i] = *(const uint4*)(g_kl + off);                               \
        rvh[i] = *(const uint4*)(g_vh + off);                               \
        rvl[i] = *(const uint4*)(g_vl + off);                               \
    } }

    LOADKV(0);
    for (int it = 0; it < SEQ/64; it++) {
        __syncthreads();
#pragma unroll
        for (int i = 0; i < 2; i++) {
            int sl = tid + i*256, row = sl >> 3, cg = sl & 7;
            *(uint4*)&sKh[row*VSTR + cg*8] = rkh[i];
            *(uint4*)&sKl[row*VSTR + cg*8] = rkl[i];
            *(uint4*)&sVh[row*VSTR + cg*8] = rvh[i];   // V stored un-transposed
            *(uint4*)&sVl[row*VSTR + cg*8] = rvl[i];
        }
        __syncthreads();
        if (it + 1 < SEQ/64) LOADKV((it+1)*64);

        float sc[8][4];
#pragma unroll
        for (int a = 0; a < 8; a++)
#pragma unroll
            for (int b = 0; b < 4; b++) sc[a][b] = 0.0f;
        // S = Q K^T : ldmatrix fragments, pass-major
#pragma unroll
        for (int c = 0; c < 4; c++) {
            const int kbase = c*16 + b_ko;
            u32 kb[8][2];
#pragma unroll
            for (int pr = 0; pr < 4; pr++)
                ldsm_x4(kb[2*pr][0], kb[2*pr][1], kb[2*pr+1][0], kb[2*pr+1][1],
                        smem_u32(&sKh[(pr*16 + b_row)*VSTR + kbase]));
#pragma unroll
            for (int nt = 0; nt < 8; nt++) mma16816(sc[nt], qfh[c], kb[nt]);
#pragma unroll
            for (int pr = 0; pr < 4; pr++)
                ldsm_x4(kb[2*pr][0], kb[2*pr][1], kb[2*pr+1][0], kb[2*pr+1][1],
                        smem_u32(&sKl[(pr*16 + b_row)*VSTR + kbase]));
#pragma unroll
            for (int nt = 0; nt < 8; nt++) mma16816(sc[nt], qfh[c], kb[nt]);
#pragma unroll
            for (int pr = 0; pr < 4; pr++)
                ldsm_x4(kb[2*pr][0], kb[2*pr][1], kb[2*pr+1][0], kb[2*pr+1][1],
                        smem_u32(&sKh[(pr*16 + b_row)*VSTR + kbase]));
#pragma unroll
            for (int nt = 0; nt < 8; nt++) mma16816(sc[nt], qfl[c], kb[nt]);
        }

        float rm0 = -1e30f, rm1 = -1e30f;
#pragma unroll
        for (int nt = 0; nt < 8; nt++) {
            rm0 = fmaxf(rm0, fmaxf(sc[nt][0], sc[nt][1]));
            rm1 = fmaxf(rm1, fmaxf(sc[nt][2], sc[nt][3]));
        }
        rm0 = fmaxf(rm0, __shfl_xor_sync(0xffffffffu, rm0, 1));
        rm0 = fmaxf(rm0, __shfl_xor_sync(0xffffffffu, rm0, 2));
        rm1 = fmaxf(rm1, __shfl_xor_sync(0xffffffffu, rm1, 1));
        rm1 = fmaxf(rm1, __shfl_xor_sync(0xffffffffu, rm1, 2));
        float mn0 = fmaxf(mi0, rm0), mn1 = fmaxf(mi1, rm1);
        float a0 = __expf(mi0 - mn0), a1 = __expf(mi1 - mn1);
        float s0 = 0.0f, s1 = 0.0f;
#pragma unroll
        for (int nt = 0; nt < 8; nt++) {
            sc[nt][0] = __expf(sc[nt][0] - mn0); s0 += sc[nt][0];
            sc[nt][1] = __expf(sc[nt][1] - mn0); s0 += sc[nt][1];
            sc[nt][2] = __expf(sc[nt][2] - mn1); s1 += sc[nt][2];
            sc[nt][3] = __expf(sc[nt][3] - mn1); s1 += sc[nt][3];
        }
        s0 += __shfl_xor_sync(0xffffffffu, s0, 1);
        s0 += __shfl_xor_sync(0xffffffffu, s0, 2);
        s1 += __shfl_xor_sync(0xffffffffu, s1, 1);
        s1 += __shfl_xor_sync(0xffffffffu, s1, 2);
        li0 = li0 * a0 + s0; li1 = li1 * a1 + s1;
        mi0 = mn0; mi1 = mn1;
#pragma unroll
        for (int nt = 0; nt < 8; nt++) {
            o[nt][0] *= a0; o[nt][1] *= a0; o[nt][2] *= a1; o[nt][3] *= a1;
        }

        // O += P V : trans-ldmatrix on [seq][d] V, pass-major per j
#pragma unroll
        for (int j = 0; j < 4; j++) {
            u32 ph[4], pl[4];
            splitpair(sc[2*j][0],   sc[2*j][1],   ph[0], pl[0]);
            splitpair(sc[2*j][2],   sc[2*j][3],   ph[1], pl[1]);
            splitpair(sc[2*j+1][0], sc[2*j+1][1], ph[2], pl[2]);
            splitpair(sc[2*j+1][2], sc[2*j+1][3], ph[3], pl[3]);
            const int krow = j*16 + v_row;
            u32 vb[8][2];
#pragma unroll
            for (int pr = 0; pr < 4; pr++)
                ldsm_x4_trans(vb[2*pr][0], vb[2*pr][1], vb[2*pr+1][0], vb[2*pr+1][1],
                              smem_u32(&sVh[krow*VSTR + pr*16 + v_col]));
#pragma unroll
            for (int nt = 0; nt < 8; nt++) mma16816(o[nt], ph, vb[nt]);
#pragma unroll
            for (int pr = 0; pr < 4; pr++)
                ldsm_x4_trans(vb[2*pr][0], vb[2*pr][1], vb[2*pr+1][0], vb[2*pr+1][1],
                              smem_u32(&sVl[krow*VSTR + pr*16 + v_col]));
#pragma unroll
            for (int nt = 0; nt < 8; nt++) mma16816(o[nt], ph, vb[nt]);
#pragma unroll
            for (int pr = 0; pr < 4; pr++)
                ldsm_x4_trans(vb[2*pr][0], vb[2*pr][1], vb[2*pr+1][0], vb[2*pr+1][1],
                              smem_u32(&sVh[krow*VSTR + pr*16 + v_col]));
#pragma unroll
            for (int nt = 0; nt < 8; nt++) mma16816(o[nt], pl, vb[nt]);
        }
    }

    float i0 = 1.0f / li0, i1 = 1.0f / li1;
    int r0 = q0 + wid*16 + g;
#pragma unroll
    for (int nt = 0; nt < 8; nt++) {
        int col = nt*8 + 2*t;
        float2 v0 = make_float2(o[nt][0]*i0, o[nt][1]*i0);
        float2 v1 = make_float2(o[nt][2]*i1, o[nt][3]*i1);
        *(float2*)&g_o[base + (size_t)r0 * HDIM + col] = v0;
        *(float2*)&g_o[base + (size_t)(r0+8) * HDIM + col] = v1;
    }
#undef LOADKV
}

// ---------------- LayerNorm (gather heads, write bf16 hi/lo) -------------------
__global__ __launch_bounds__(256)
void ln_kernel(const float* __restrict__ gamma, const float* __restrict__ beta) {
    int bn = blockIdx.x;
    int b = bn >> 11;
    int n = bn & 2047;

    float vals[4];
    float s = 0.0f, ss = 0.0f;
#pragma unroll
    for (int ti = 0; ti < 4; ti++) {
        int c = threadIdx.x + ti * 256;
        int h = c >> 6, d = c & 63;
        float v = g_o[(((size_t)(b * HEADS + h)) * SEQ + n) * HDIM + d];
        vals[ti] = v; s += v; ss += v * v;
    }
#pragma unroll
    for (int m = 16; m; m >>= 1) {
        s  += __shfl_xor_sync(0xffffffffu, s, m);
        ss += __shfl_xor_sync(0xffffffffu, ss, m);
    }
    __shared__ float rs[8], rss[8];
    int w = threadIdx.x >> 5, lanei = threadIdx.x & 31;
    if (lanei == 0) { rs[w] = s; rss[w] = ss; }
    __syncthreads();
    float st = 0.0f, sst = 0.0f;
#pragma unroll
    for (int i = 0; i < 8; i++) { st += rs[i]; sst += rss[i]; }

    float mean = st * (1.0f / 1024.0f);
    float var  = sst * (1.0f / 1024.0f) - mean * mean;
    float r = rsqrtf(var + 1e-5f);
#pragma unroll
    for (int ti = 0; ti < 4; ti++) {
        int c = threadIdx.x + ti * 256;
        float f = (vals[ti] - mean) * r * gamma[c] + beta[c];
        unsigned short hh, ll; split1(f, hh, ll);
        g_lnh[(size_t)bn * DIM + c] = hh;
        g_lnl[(size_t)bn * DIM + c] = ll;
    }
}

// ---------------- launch --------------------------------------------------------
extern "C" void kernel_launch(void* const* d_in, const int* in_sizes, int n_in,
                              void* d_out, int out_size) {
    const float* x      = (const float*)d_in[0];
    const float* pe     = (const float*)d_in[1];
    const float* qkv_w  = (const float*)d_in[2];
    const float* q_bias = (const float*)d_in[3];
    const float* v_bias = (const float*)d_in[4];
    const float* gamma  = (const float*)d_in[5];
    const float* beta   = (const float*)d_in[6];
    const float* proj_w = (const float*)d_in[7];
    const float* proj_b = (const float*)d_in[8];
    float* out = (float*)d_out;

    void *p_bias3;
    void *p_xh, *p_xl, *p_wh, *p_wl, *p_pwh, *p_pwl, *p_lnh, *p_lnl;
    cudaGetSymbolAddress(&p_bias3, g_bias3);
    cudaGetSymbolAddress(&p_xh, g_xh);   cudaGetSymbolAddress(&p_xl, g_xl);
    cudaGetSymbolAddress(&p_wh, g_wh);   cudaGetSymbolAddress(&p_wl, g_wl);
    cudaGetSymbolAddress(&p_pwh, g_pwh); cudaGetSymbolAddress(&p_pwl, g_pwl);
    cudaGetSymbolAddress(&p_lnh, g_lnh); cudaGetSymbolAddress(&p_lnl, g_lnl);

    cudaFuncSetAttribute(gemm_bf16x3_v5,
                         cudaFuncAttributeMaxDynamicSharedMemorySize, GEMM_DSMEM);

    // 1) fused splits + bias
    fused_split_kernel<<<(TOTSPLIT + 255)/256, 256>>>(x, qkv_w, proj_w, q_bias, v_bias);

    // 2) QKV GEMM with fused bias + RoPE + hi/lo split epilogue
    gemm_bf16x3_v5<<<dim3(QKVN/BN, MROWS/BM), 256, GEMM_DSMEM>>>(
        (const ushortT*)p_xh, (const ushortT*)p_xl,
        (const ushortT*)p_wh, (const ushortT*)p_wl,
        (const float*)p_bias3, nullptr, MROWS, QKVN, DIM, 1, pe);

    // 3) k_mean
    kmean_kernel<<<(BATCH*SEQ*HDIM)/256, 256>>>(out + (size_t)MROWS * DIM);

    // 4) flash attention (4th launch -> profiled)
    flash_bf16x3<<<dim3(SEQ/128, BH), 256>>>();

    // 5) layernorm
    ln_kernel<<<MROWS, 256>>>(gamma, beta);

    // 6) projection GEMM -> d_out
    gemm_bf16x3_v5<<<dim3(DIM/BN, MROWS/BM), 256, GEMM_DSMEM>>>(
        (const ushortT*)p_lnh, (const ushortT*)p_lnl,
        (const ushortT*)p_pwh, (const ushortT*)p_pwl,
        proj_b, out, MROWS, DIM, DIM, 0, nullptr);
}